// round 3
// baseline (speedup 1.0000x reference)
#include <cuda_runtime.h>
#include <math.h>

#define D 128
#define KNBR 5
#define NMAX 300000

#define BM 64
#define BN 128
#define BK 16

// ---------------- scratch (static device memory; no allocations allowed) ----
__device__ float g_Q1[(size_t)NMAX * D];
__device__ float g_K1[(size_t)NMAX * D];
__device__ float g_V1[(size_t)NMAX * D];
__device__ float g_K2[(size_t)NMAX * D];
__device__ float g_V2[(size_t)NMAX * D];
__device__ float g_Q2[(size_t)NMAX * D];
__device__ float g_ATT[(size_t)NMAX * D];
__device__ float g_XA[(size_t)NMAX * D];
__device__ float g_XB[(size_t)NMAX * D];
__device__ float g_H[(size_t)NMAX * 2 * D];
__device__ float g_rs[NMAX];
__device__ int   g_validbyte;

// ---------------- detect whether nbr_valid is byte-bool or int32 ------------
// If int32 (values 0/1), every byte at offset %4 != 0 is zero.
// If byte-bool, element 5 == valid[1][0] == 1 (deg>=1), byte offset 5 (%4==1),
// so a nonzero byte at such an offset is guaranteed within the first 4096.
__global__ void detect_valid_kernel(const unsigned char* __restrict__ p, int nelem) {
    if (threadIdx.x == 0) g_validbyte = 0;
    __syncthreads();
    int lim = nelem < 4096 ? nelem : 4096;
    int found = 0;
    for (int j = threadIdx.x; j < lim; j += blockDim.x)
        if ((j & 3) && p[j]) found = 1;
    if (found) g_validbyte = 1;
}

// ---------------- per-node feature rowsum (for the mask) --------------------
__global__ void rowsum_kernel(const float* __restrict__ feat, float* __restrict__ rs, int N) {
    int warp = (blockIdx.x * blockDim.x + threadIdx.x) >> 5;
    int lane = threadIdx.x & 31;
    if (warp >= N) return;
    float4 v = ((const float4*)feat)[(size_t)warp * 32 + lane];
    float s = v.x + v.y + v.z + v.w;
    #pragma unroll
    for (int o = 16; o; o >>= 1) s += __shfl_xor_sync(0xffffffffu, s, o);
    if (lane == 0) rs[warp] = s;
}

// ---------------- fused 5-way projection GEMM: Y[p] = X @ W[p] --------------
// blockIdx.x = projection id (0..4), blockIdx.y = row tile -> consecutive
// blocks share the same X tile (L2 reuse).
struct Proj5 { const float* W[5]; float* Y[5]; };

__global__ void gemm_proj5(const float* __restrict__ X, Proj5 p, int M) {
    __shared__ float As[BK][BM];
    __shared__ float Bs[BK][BN];
    const float* W = p.W[blockIdx.x];
    float*       Y = p.Y[blockIdx.x];
    int row0 = blockIdx.y * BM;
    int tid = threadIdx.x;
    int tx = tid & 15, ty = tid >> 4;
    float acc[4][8] = {};
    int arow = tid >> 2;
    int akc  = (tid & 3) * 4;
    int brow = tid >> 4;
    int bcol = (tid & 15) * 8;
    for (int k0 = 0; k0 < D; k0 += BK) {
        float4 av = make_float4(0.f, 0.f, 0.f, 0.f);
        if (row0 + arow < M) av = *(const float4*)&X[(size_t)(row0 + arow) * D + k0 + akc];
        As[akc + 0][arow] = av.x; As[akc + 1][arow] = av.y;
        As[akc + 2][arow] = av.z; As[akc + 3][arow] = av.w;
        const float* wp = &W[(size_t)(k0 + brow) * D + bcol];
        *(float4*)&Bs[brow][bcol]     = *(const float4*)wp;
        *(float4*)&Bs[brow][bcol + 4] = *(const float4*)(wp + 4);
        __syncthreads();
        #pragma unroll
        for (int k = 0; k < BK; k++) {
            float4 a4 = *(float4*)&As[k][ty * 4];
            float a[4] = {a4.x, a4.y, a4.z, a4.w};
            float4 b0 = *(float4*)&Bs[k][tx * 8];
            float4 b1 = *(float4*)&Bs[k][tx * 8 + 4];
            float b[8] = {b0.x, b0.y, b0.z, b0.w, b1.x, b1.y, b1.z, b1.w};
            #pragma unroll
            for (int i = 0; i < 4; i++)
                #pragma unroll
                for (int j = 0; j < 8; j++) acc[i][j] += a[i] * b[j];
        }
        __syncthreads();
    }
    #pragma unroll
    for (int i = 0; i < 4; i++) {
        int row = row0 + ty * 4 + i;
        if (row >= M) continue;
        #pragma unroll
        for (int j0 = 0; j0 < 8; j0 += 4) {
            int col = tx * 8 + j0;
            float4 o = make_float4(acc[i][j0], acc[i][j0 + 1], acc[i][j0 + 2], acc[i][j0 + 3]);
            *(float4*)&Y[(size_t)row * D + col] = o;
        }
    }
}

// ---------------- GEMM + bias + elementwise activation ----------------------
// ACT: 0 = none, 1 = relu, 2 = tanh
template <int ACT>
__global__ void gemm_act(const float* __restrict__ X, const float* __restrict__ W,
                         const float* __restrict__ bias, float* __restrict__ Y,
                         int M, int Kd, int Ncols) {
    __shared__ float As[BK][BM];
    __shared__ float Bs[BK][BN];
    int row0 = blockIdx.x * BM;
    int col0 = blockIdx.y * BN;
    int tid = threadIdx.x;
    int tx = tid & 15, ty = tid >> 4;
    float acc[4][8] = {};
    int arow = tid >> 2;
    int akc  = (tid & 3) * 4;
    int brow = tid >> 4;
    int bcol = (tid & 15) * 8;
    for (int k0 = 0; k0 < Kd; k0 += BK) {
        float4 av = make_float4(0.f, 0.f, 0.f, 0.f);
        if (row0 + arow < M) av = *(const float4*)&X[(size_t)(row0 + arow) * Kd + k0 + akc];
        As[akc + 0][arow] = av.x; As[akc + 1][arow] = av.y;
        As[akc + 2][arow] = av.z; As[akc + 3][arow] = av.w;
        float4 b0 = make_float4(0.f, 0.f, 0.f, 0.f);
        float4 b1 = make_float4(0.f, 0.f, 0.f, 0.f);
        if (col0 + bcol < Ncols) {
            const float* wp = &W[(size_t)(k0 + brow) * Ncols + col0 + bcol];
            b0 = *(const float4*)wp;
            b1 = *(const float4*)(wp + 4);
        }
        *(float4*)&Bs[brow][bcol]     = b0;
        *(float4*)&Bs[brow][bcol + 4] = b1;
        __syncthreads();
        #pragma unroll
        for (int k = 0; k < BK; k++) {
            float4 a4 = *(float4*)&As[k][ty * 4];
            float a[4] = {a4.x, a4.y, a4.z, a4.w};
            float4 bb0 = *(float4*)&Bs[k][tx * 8];
            float4 bb1 = *(float4*)&Bs[k][tx * 8 + 4];
            float b[8] = {bb0.x, bb0.y, bb0.z, bb0.w, bb1.x, bb1.y, bb1.z, bb1.w};
            #pragma unroll
            for (int i = 0; i < 4; i++)
                #pragma unroll
                for (int j = 0; j < 8; j++) acc[i][j] += a[i] * b[j];
        }
        __syncthreads();
    }
    const bool hasb = (bias != nullptr);
    #pragma unroll
    for (int i = 0; i < 4; i++) {
        int row = row0 + ty * 4 + i;
        if (row >= M) continue;
        #pragma unroll
        for (int j0 = 0; j0 < 8; j0 += 4) {
            int col = col0 + tx * 8 + j0;
            if (col >= Ncols) continue;
            float4 o;
            o.x = acc[i][j0 + 0] + (hasb ? bias[col + 0] : 0.f);
            o.y = acc[i][j0 + 1] + (hasb ? bias[col + 1] : 0.f);
            o.z = acc[i][j0 + 2] + (hasb ? bias[col + 2] : 0.f);
            o.w = acc[i][j0 + 3] + (hasb ? bias[col + 3] : 0.f);
            if (ACT == 1) {
                o.x = fmaxf(o.x, 0.f); o.y = fmaxf(o.y, 0.f);
                o.z = fmaxf(o.z, 0.f); o.w = fmaxf(o.w, 0.f);
            } else if (ACT == 2) {
                o.x = tanhf(o.x); o.y = tanhf(o.y);
                o.z = tanhf(o.z); o.w = tanhf(o.w);
            }
            *(float4*)&Y[(size_t)row * Ncols + col] = o;
        }
    }
}

// ---------------- GEMM + bias + residual + LayerNorm (Ncols = 128) ----------
__global__ void gemm_ln(const float* __restrict__ X, const float* __restrict__ W,
                        const float* __restrict__ bias, const float* __restrict__ res,
                        const float* __restrict__ gam, const float* __restrict__ bet,
                        float* __restrict__ Y, int M, int Kd) {
    __shared__ float As[BK][BM];
    __shared__ float Bs[BK][BN];
    __shared__ float Cs[BM][BN + 4];
    int row0 = blockIdx.x * BM;
    int tid = threadIdx.x;
    int tx = tid & 15, ty = tid >> 4;
    float acc[4][8] = {};
    int arow = tid >> 2;
    int akc  = (tid & 3) * 4;
    int brow = tid >> 4;
    int bcol = (tid & 15) * 8;
    for (int k0 = 0; k0 < Kd; k0 += BK) {
        float4 av = make_float4(0.f, 0.f, 0.f, 0.f);
        if (row0 + arow < M) av = *(const float4*)&X[(size_t)(row0 + arow) * Kd + k0 + akc];
        As[akc + 0][arow] = av.x; As[akc + 1][arow] = av.y;
        As[akc + 2][arow] = av.z; As[akc + 3][arow] = av.w;
        const float* wp = &W[(size_t)(k0 + brow) * D + bcol];
        *(float4*)&Bs[brow][bcol]     = *(const float4*)wp;
        *(float4*)&Bs[brow][bcol + 4] = *(const float4*)(wp + 4);
        __syncthreads();
        #pragma unroll
        for (int k = 0; k < BK; k++) {
            float4 a4 = *(float4*)&As[k][ty * 4];
            float a[4] = {a4.x, a4.y, a4.z, a4.w};
            float4 bb0 = *(float4*)&Bs[k][tx * 8];
            float4 bb1 = *(float4*)&Bs[k][tx * 8 + 4];
            float b[8] = {bb0.x, bb0.y, bb0.z, bb0.w, bb1.x, bb1.y, bb1.z, bb1.w};
            #pragma unroll
            for (int i = 0; i < 4; i++)
                #pragma unroll
                for (int j = 0; j < 8; j++) acc[i][j] += a[i] * b[j];
        }
        __syncthreads();
    }
    #pragma unroll
    for (int i = 0; i < 4; i++)
        #pragma unroll
        for (int j0 = 0; j0 < 8; j0 += 4)
            *(float4*)&Cs[ty * 4 + i][tx * 8 + j0] =
                make_float4(acc[i][j0], acc[i][j0 + 1], acc[i][j0 + 2], acc[i][j0 + 3]);
    __syncthreads();

    int wid = tid >> 5, lane = tid & 31;
    for (int r = wid; r < BM; r += 8) {
        int row = row0 + r;
        if (row >= M) continue;
        float4 c  = *(float4*)&Cs[r][lane * 4];
        float4 rv = ((const float4*)res)[(size_t)row * 32 + lane];
        float4 bb = ((const float4*)bias)[lane];
        float v0 = c.x + rv.x + bb.x;
        float v1 = c.y + rv.y + bb.y;
        float v2 = c.z + rv.z + bb.z;
        float v3 = c.w + rv.w + bb.w;
        float s  = v0 + v1 + v2 + v3;
        float sq = v0 * v0 + v1 * v1 + v2 * v2 + v3 * v3;
        #pragma unroll
        for (int o = 16; o; o >>= 1) {
            s  += __shfl_xor_sync(0xffffffffu, s, o);
            sq += __shfl_xor_sync(0xffffffffu, sq, o);
        }
        float mean = s * (1.f / 128.f);
        float var  = sq * (1.f / 128.f) - mean * mean;
        float rstd = rsqrtf(var + 1e-5f);
        float4 gg = ((const float4*)gam)[lane];
        float4 ee = ((const float4*)bet)[lane];
        float4 o;
        o.x = (v0 - mean) * rstd * gg.x + ee.x;
        o.y = (v1 - mean) * rstd * gg.y + ee.y;
        o.z = (v2 - mean) * rstd * gg.z + ee.z;
        o.w = (v3 - mean) * rstd * gg.w + ee.w;
        ((float4*)Y)[(size_t)row * 32 + lane] = o;
    }
}

// ---------------- warp-per-node attention -----------------------------------
// lane l holds floats [4l, 4l+4); head h = l/4 (dh=16 -> 4 lanes per head).
__global__ void attn_kernel(const float* __restrict__ Q, const float* __restrict__ Kp,
                            const float* __restrict__ Vp, const int* __restrict__ nbr,
                            const void* __restrict__ validp, const float* __restrict__ rs,
                            float* __restrict__ out, int N) {
    int warp = (blockIdx.x * blockDim.x + threadIdx.x) >> 5;
    int lane = threadIdx.x & 31;
    if (warp >= N) return;
    int i = warp;
    float4 q = ((const float4*)Q)[(size_t)i * 32 + lane];
    bool isbyte = (g_validbyte != 0);
    float d[KNBR];
    float4 v[KNBR];
    #pragma unroll
    for (int j = 0; j < KNBR; j++) {
        int nb = nbr[(size_t)i * KNBR + j];
        int vld = isbyte ? (int)((const unsigned char*)validp)[(size_t)i * KNBR + j]
                         : ((const int*)validp)[(size_t)i * KNBR + j];
        bool masked = (vld == 0) || (rs[nb] == 0.0f);
        float4 k4 = ((const float4*)Kp)[(size_t)nb * 32 + lane];
        v[j]      = ((const float4*)Vp)[(size_t)nb * 32 + lane];
        float p = q.x * k4.x + q.y * k4.y + q.z * k4.z + q.w * k4.w;
        p += __shfl_xor_sync(0xffffffffu, p, 1);
        p += __shfl_xor_sync(0xffffffffu, p, 2);
        d[j] = masked ? -1e30f : p * 0.25f;   // dh^-0.5 = 1/4
    }
    float m = d[0];
    #pragma unroll
    for (int j = 1; j < KNBR; j++) m = fmaxf(m, d[j]);
    float e[KNBR], s = 0.f;
    #pragma unroll
    for (int j = 0; j < KNBR; j++) { e[j] = __expf(d[j] - m); s += e[j]; }
    float inv = 1.f / s;
    float4 o = make_float4(0.f, 0.f, 0.f, 0.f);
    #pragma unroll
    for (int j = 0; j < KNBR; j++) {
        float a = e[j] * inv;
        o.x += a * v[j].x; o.y += a * v[j].y; o.z += a * v[j].z; o.w += a * v[j].w;
    }
    ((float4*)out)[(size_t)i * 32 + lane] = o;
}

// ---------------- host orchestration ----------------------------------------
extern "C" void kernel_launch(void* const* d_in, const int* in_sizes, int n_in,
                              void* d_out, int out_size) {
    const float* feat  = (const float*)d_in[0];
    const int*   nbr   = (const int*)d_in[1];
    const void*  valid = d_in[2];
    const float* wq1 = (const float*)d_in[3];
    const float* wk1 = (const float*)d_in[4];
    const float* wv1 = (const float*)d_in[5];
    const float* wo1 = (const float*)d_in[6];
    const float* bo1 = (const float*)d_in[7];
    const float* w1a = (const float*)d_in[8];
    const float* b1a = (const float*)d_in[9];
    const float* w1b = (const float*)d_in[10];
    const float* b1b = (const float*)d_in[11];
    const float* g1a = (const float*)d_in[12];
    const float* be1a= (const float*)d_in[13];
    const float* g1b = (const float*)d_in[14];
    const float* be1b= (const float*)d_in[15];
    const float* wq2 = (const float*)d_in[16];
    const float* wk2 = (const float*)d_in[17];
    const float* wv2 = (const float*)d_in[18];
    const float* wo2 = (const float*)d_in[19];
    const float* bo2 = (const float*)d_in[20];
    const float* w2a = (const float*)d_in[21];
    const float* b2a = (const float*)d_in[22];
    const float* w2b = (const float*)d_in[23];
    const float* b2b = (const float*)d_in[24];
    const float* g2a = (const float*)d_in[25];
    const float* be2a= (const float*)d_in[26];
    const float* g2b = (const float*)d_in[27];
    const float* be2b= (const float*)d_in[28];
    const float* w4  = (const float*)d_in[29];
    const float* b4  = (const float*)d_in[30];

    int N = in_sizes[0] / D;

    float *Q1, *K1, *V1, *K2, *V2, *Q2, *ATT, *XA, *XB, *H, *RS;
    cudaGetSymbolAddress((void**)&Q1,  g_Q1);
    cudaGetSymbolAddress((void**)&K1,  g_K1);
    cudaGetSymbolAddress((void**)&V1,  g_V1);
    cudaGetSymbolAddress((void**)&K2,  g_K2);
    cudaGetSymbolAddress((void**)&V2,  g_V2);
    cudaGetSymbolAddress((void**)&Q2,  g_Q2);
    cudaGetSymbolAddress((void**)&ATT, g_ATT);
    cudaGetSymbolAddress((void**)&XA,  g_XA);
    cudaGetSymbolAddress((void**)&XB,  g_XB);
    cudaGetSymbolAddress((void**)&H,   g_H);
    cudaGetSymbolAddress((void**)&RS,  g_rs);

    int MB  = (N + BM - 1) / BM;
    int WPB = (N + 7) / 8;  // warp-per-node kernels, 8 warps/block

    detect_valid_kernel<<<1, 1024>>>((const unsigned char*)valid, N * KNBR);
    rowsum_kernel<<<WPB, 256>>>(feat, RS, N);

    Proj5 p;
    p.W[0] = wq1; p.W[1] = wk1; p.W[2] = wv1; p.W[3] = wk2; p.W[4] = wv2;
    p.Y[0] = Q1;  p.Y[1] = K1;  p.Y[2] = V1;  p.Y[3] = K2;  p.Y[4] = V2;
    gemm_proj5<<<dim3(5, MB), 256>>>(feat, p, N);

    // ---- layer 1 ----
    attn_kernel<<<WPB, 256>>>(Q1, K1, V1, nbr, valid, RS, ATT, N);
    gemm_ln<<<MB, 256>>>(ATT, wo1, bo1, feat, g1a, be1a, XA, N, D);          // XA = LN(feat + att@wo1)
    gemm_act<1><<<dim3(MB, 2), 256>>>(XA, w1a, b1a, H, N, D, 2 * D);          // H  = relu(XA@w1a + b1a)
    gemm_ln<<<MB, 256>>>(H, w1b, b1b, XA, g1b, be1b, XB, N, 2 * D);           // XB = LN(XA + H@w1b + b1b)

    // ---- layer 2 ----
    gemm_act<0><<<dim3(MB, 1), 256>>>(XB, wq2, nullptr, Q2, N, D, D);         // Q2 = XB@wq2
    attn_kernel<<<WPB, 256>>>(Q2, K2, V2, nbr, valid, RS, ATT, N);
    gemm_ln<<<MB, 256>>>(ATT, wo2, bo2, XB, g2a, be2a, XA, N, D);             // XA = LN(XB + att@wo2)
    gemm_act<1><<<dim3(MB, 2), 256>>>(XA, w2a, b2a, H, N, D, 2 * D);          // H  = relu(XA@w2a + b2a)
    gemm_ln<<<MB, 256>>>(H, w2b, b2b, XA, g2b, be2b, XB, N, 2 * D);           // XB = LN(XA + H@w2b + b2b)

    // ---- head ----
    gemm_act<2><<<dim3(MB, 1), 256>>>(XB, w4, b4, (float*)d_out, N, D, D / 2);
}

// round 4
// speedup vs baseline: 2.2541x; 2.2541x over previous
#include <cuda_runtime.h>
#include <math.h>

#define D 128
#define KNBR 5
#define NMAX 300000

// ---------------- scratch (static device memory; no allocations allowed) ----
__device__ float g_Q1[(size_t)NMAX * D];
__device__ float g_K1[(size_t)NMAX * D];
__device__ float g_V1[(size_t)NMAX * D];
__device__ float g_K2[(size_t)NMAX * D];
__device__ float g_V2[(size_t)NMAX * D];
__device__ float g_Q2[(size_t)NMAX * D];
__device__ float g_ATT[(size_t)NMAX * D];
__device__ float g_XA[(size_t)NMAX * D];
__device__ float g_XB[(size_t)NMAX * D];
__device__ float g_H[(size_t)NMAX * 2 * D];
__device__ float g_rs[NMAX];
__device__ int   g_validbyte;

// ---------------- detect whether nbr_valid is byte-bool or int32 ------------
__global__ void detect_valid_kernel(const unsigned char* __restrict__ p, int nelem) {
    if (threadIdx.x == 0) g_validbyte = 0;
    __syncthreads();
    int lim = nelem < 4096 ? nelem : 4096;
    int found = 0;
    for (int j = threadIdx.x; j < lim; j += blockDim.x)
        if ((j & 3) && p[j]) found = 1;
    if (found) g_validbyte = 1;
}

// ---------------- per-node feature rowsum (for the mask) --------------------
__global__ void rowsum_kernel(const float* __restrict__ feat, float* __restrict__ rs, int N) {
    int warp = (blockIdx.x * blockDim.x + threadIdx.x) >> 5;
    int lane = threadIdx.x & 31;
    if (warp >= N) return;
    float4 v = ((const float4*)feat)[(size_t)warp * 32 + lane];
    float s = v.x + v.y + v.z + v.w;
    #pragma unroll
    for (int o = 16; o; o >>= 1) s += __shfl_xor_sync(0xffffffffu, s, o);
    if (lane == 0) rs[warp] = s;
}

// ---------------- tf32 helpers ----------------------------------------------
__device__ __forceinline__ unsigned f2tf32(float f) {
    unsigned u;
    asm("cvt.rna.tf32.f32 %0, %1;" : "=r"(u) : "f"(f));
    return u;
}

__device__ __forceinline__ void mma_tf32(float* c, const unsigned* a, const unsigned* b) {
    asm volatile(
        "mma.sync.aligned.m16n8k8.row.col.f32.tf32.tf32.f32 "
        "{%0,%1,%2,%3}, {%4,%5,%6,%7}, {%8,%9}, {%0,%1,%2,%3};"
        : "+f"(c[0]), "+f"(c[1]), "+f"(c[2]), "+f"(c[3])
        : "r"(a[0]), "r"(a[1]), "r"(a[2]), "r"(a[3]), "r"(b[0]), "r"(b[1]));
}

// ---------------- tensor-core GEMM core: 128x128 tile, 256 threads ----------
// warp grid 4(M) x 2(N); warp tile 32x64; mma m16n8k8 tf32.
// As[k][row] pad 136 -> conflict-free frag loads; Bs[k][n] pad 136.
__device__ __forceinline__ void mma_core(
    unsigned (*As)[136], unsigned (*Bs)[136],
    const float* __restrict__ X, const float* __restrict__ W,
    int M, int Kd, int Ncols, int row0, int col0,
    int tid, int lane, int mrow, int ncol,
    float (&c)[2][8][4])
{
    int r  = tid & 127;            // A staging: row
    int kh = (tid >> 7) * 8;       // A staging: k-half
    int kk = tid >> 4;             // B staging: k row
    int c8 = (tid & 15) * 8;       // B staging: col base
    int grow = row0 + r;
    bool rok = grow < M;
    size_t xbase = (size_t)grow * Kd;

    for (int k0 = 0; k0 < Kd; k0 += 16) {
        #pragma unroll
        for (int it = 0; it < 2; it++) {
            int kc = kh + it * 4;
            float4 v = make_float4(0.f, 0.f, 0.f, 0.f);
            if (rok) v = *(const float4*)&X[xbase + k0 + kc];
            As[kc + 0][r] = f2tf32(v.x);
            As[kc + 1][r] = f2tf32(v.y);
            As[kc + 2][r] = f2tf32(v.z);
            As[kc + 3][r] = f2tf32(v.w);
        }
        #pragma unroll
        for (int it = 0; it < 2; it++) {
            int cc = c8 + it * 4;
            float4 v = make_float4(0.f, 0.f, 0.f, 0.f);
            if (col0 + cc < Ncols)
                v = *(const float4*)&W[(size_t)(k0 + kk) * Ncols + col0 + cc];
            uint4 t;
            t.x = f2tf32(v.x); t.y = f2tf32(v.y);
            t.z = f2tf32(v.z); t.w = f2tf32(v.w);
            *(uint4*)&Bs[kk][cc] = t;
        }
        __syncthreads();
        #pragma unroll
        for (int ks = 0; ks < 16; ks += 8) {
            int kq = ks + (lane & 3);
            unsigned a[2][4], b[8][2];
            #pragma unroll
            for (int mt = 0; mt < 2; mt++) {
                int row = mrow + mt * 16 + (lane >> 2);
                a[mt][0] = As[kq][row];
                a[mt][1] = As[kq][row + 8];
                a[mt][2] = As[kq + 4][row];
                a[mt][3] = As[kq + 4][row + 8];
            }
            #pragma unroll
            for (int nt = 0; nt < 8; nt++) {
                int col = ncol + nt * 8 + (lane >> 2);
                b[nt][0] = Bs[kq][col];
                b[nt][1] = Bs[kq + 4][col];
            }
            #pragma unroll
            for (int mt = 0; mt < 2; mt++)
                #pragma unroll
                for (int nt = 0; nt < 8; nt++)
                    mma_tf32(c[mt][nt], a[mt], b[nt]);
        }
        __syncthreads();
    }
}

// EPI: 0 = bias(optional), 1 = bias+relu, 2 = bias+tanh, 3 = bias+residual+LayerNorm (Ncols==128)
template <int EPI>
__global__ void __launch_bounds__(256) gemm_mma(
    const float* __restrict__ X, const float* __restrict__ W,
    const float* __restrict__ bias, const float* __restrict__ res,
    const float* __restrict__ gam, const float* __restrict__ bet,
    float* __restrict__ Y, int M, int Kd, int Ncols)
{
    __shared__ unsigned As[16][136];
    __shared__ unsigned Bs[16][136];
    int row0 = blockIdx.x * 128;
    int col0 = blockIdx.y * 128;
    int tid  = threadIdx.x;
    int lane = tid & 31;
    int warp = tid >> 5;
    int mrow = (warp >> 1) * 32;
    int ncol = (warp & 1) * 64;

    float c[2][8][4] = {};
    mma_core(As, Bs, X, W, M, Kd, Ncols, row0, col0, tid, lane, mrow, ncol, c);

    if (EPI != 3) {
        const bool hasb = (bias != nullptr);
        #pragma unroll
        for (int mt = 0; mt < 2; mt++)
            #pragma unroll
            for (int nt = 0; nt < 8; nt++) {
                int col = col0 + ncol + nt * 8 + (lane & 3) * 2;
                if (col >= Ncols) continue;
                float bx = 0.f, by = 0.f;
                if (hasb) { float2 bb = *(const float2*)&bias[col]; bx = bb.x; by = bb.y; }
                #pragma unroll
                for (int rh = 0; rh < 2; rh++) {
                    int row = row0 + mrow + mt * 16 + rh * 8 + (lane >> 2);
                    if (row >= M) continue;
                    float x0 = c[mt][nt][rh * 2 + 0] + bx;
                    float x1 = c[mt][nt][rh * 2 + 1] + by;
                    if (EPI == 1) { x0 = fmaxf(x0, 0.f); x1 = fmaxf(x1, 0.f); }
                    if (EPI == 2) { x0 = tanhf(x0); x1 = tanhf(x1); }
                    *(float2*)&Y[(size_t)row * Ncols + col] = make_float2(x0, x1);
                }
            }
    } else {
        // LayerNorm epilogue (Ncols == 128, col0 == 0)
        float2* red = (float2*)&As[0][0];    // 128 rows x 2 warp-cols, reuse As
        int warpN = warp & 1;
        #pragma unroll
        for (int mt = 0; mt < 2; mt++)
            #pragma unroll
            for (int rh = 0; rh < 2; rh++) {
                int rl  = mrow + mt * 16 + rh * 8 + (lane >> 2);
                int row = row0 + rl;
                bool ok = row < M;
                float s = 0.f, sq = 0.f;
                #pragma unroll
                for (int nt = 0; nt < 8; nt++) {
                    int col = ncol + nt * 8 + (lane & 3) * 2;
                    float2 rr = ok ? *(const float2*)&res[(size_t)row * 128 + col]
                                   : make_float2(0.f, 0.f);
                    float2 bb = *(const float2*)&bias[col];
                    float x0 = c[mt][nt][rh * 2 + 0] + rr.x + bb.x;
                    float x1 = c[mt][nt][rh * 2 + 1] + rr.y + bb.y;
                    c[mt][nt][rh * 2 + 0] = x0;
                    c[mt][nt][rh * 2 + 1] = x1;
                    s += x0 + x1;
                    sq += x0 * x0 + x1 * x1;
                }
                s  += __shfl_xor_sync(0xffffffffu, s, 1);
                s  += __shfl_xor_sync(0xffffffffu, s, 2);
                sq += __shfl_xor_sync(0xffffffffu, sq, 1);
                sq += __shfl_xor_sync(0xffffffffu, sq, 2);
                if ((lane & 3) == 0) red[rl * 2 + warpN] = make_float2(s, sq);
            }
        __syncthreads();
        #pragma unroll
        for (int mt = 0; mt < 2; mt++)
            #pragma unroll
            for (int rh = 0; rh < 2; rh++) {
                int rl  = mrow + mt * 16 + rh * 8 + (lane >> 2);
                int row = row0 + rl;
                float2 e0 = red[rl * 2 + 0];
                float2 e1 = red[rl * 2 + 1];
                float s = e0.x + e1.x, sq = e0.y + e1.y;
                float mean = s * (1.f / 128.f);
                float var  = sq * (1.f / 128.f) - mean * mean;
                float rstd = rsqrtf(var + 1e-5f);
                if (row < M) {
                    #pragma unroll
                    for (int nt = 0; nt < 8; nt++) {
                        int col = ncol + nt * 8 + (lane & 3) * 2;
                        float2 gg = *(const float2*)&gam[col];
                        float2 ee = *(const float2*)&bet[col];
                        float2 o;
                        o.x = (c[mt][nt][rh * 2 + 0] - mean) * rstd * gg.x + ee.x;
                        o.y = (c[mt][nt][rh * 2 + 1] - mean) * rstd * gg.y + ee.y;
                        *(float2*)&Y[(size_t)row * 128 + col] = o;
                    }
                }
            }
    }
}

// ---------------- warp-per-node attention (82% of HBM; unchanged) -----------
__global__ void attn_kernel(const float* __restrict__ Q, const float* __restrict__ Kp,
                            const float* __restrict__ Vp, const int* __restrict__ nbr,
                            const void* __restrict__ validp, const float* __restrict__ rs,
                            float* __restrict__ out, int N) {
    int warp = (blockIdx.x * blockDim.x + threadIdx.x) >> 5;
    int lane = threadIdx.x & 31;
    if (warp >= N) return;
    int i = warp;
    float4 q = ((const float4*)Q)[(size_t)i * 32 + lane];
    bool isbyte = (g_validbyte != 0);
    float d[KNBR];
    float4 v[KNBR];
    #pragma unroll
    for (int j = 0; j < KNBR; j++) {
        int nb = nbr[(size_t)i * KNBR + j];
        int vld = isbyte ? (int)((const unsigned char*)validp)[(size_t)i * KNBR + j]
                         : ((const int*)validp)[(size_t)i * KNBR + j];
        bool masked = (vld == 0) || (rs[nb] == 0.0f);
        float4 k4 = ((const float4*)Kp)[(size_t)nb * 32 + lane];
        v[j]      = ((const float4*)Vp)[(size_t)nb * 32 + lane];
        float p = q.x * k4.x + q.y * k4.y + q.z * k4.z + q.w * k4.w;
        p += __shfl_xor_sync(0xffffffffu, p, 1);
        p += __shfl_xor_sync(0xffffffffu, p, 2);
        d[j] = masked ? -1e30f : p * 0.25f;   // dh^-0.5 = 1/4
    }
    float m = d[0];
    #pragma unroll
    for (int j = 1; j < KNBR; j++) m = fmaxf(m, d[j]);
    float e[KNBR], s = 0.f;
    #pragma unroll
    for (int j = 0; j < KNBR; j++) { e[j] = __expf(d[j] - m); s += e[j]; }
    float inv = 1.f / s;
    float4 o = make_float4(0.f, 0.f, 0.f, 0.f);
    #pragma unroll
    for (int j = 0; j < KNBR; j++) {
        float a = e[j] * inv;
        o.x += a * v[j].x; o.y += a * v[j].y; o.z += a * v[j].z; o.w += a * v[j].w;
    }
    ((float4*)out)[(size_t)i * 32 + lane] = o;
}

// ---------------- host orchestration ----------------------------------------
extern "C" void kernel_launch(void* const* d_in, const int* in_sizes, int n_in,
                              void* d_out, int out_size) {
    const float* feat  = (const float*)d_in[0];
    const int*   nbr   = (const int*)d_in[1];
    const void*  valid = d_in[2];
    const float* wq1 = (const float*)d_in[3];
    const float* wk1 = (const float*)d_in[4];
    const float* wv1 = (const float*)d_in[5];
    const float* wo1 = (const float*)d_in[6];
    const float* bo1 = (const float*)d_in[7];
    const float* w1a = (const float*)d_in[8];
    const float* b1a = (const float*)d_in[9];
    const float* w1b = (const float*)d_in[10];
    const float* b1b = (const float*)d_in[11];
    const float* g1a = (const float*)d_in[12];
    const float* be1a= (const float*)d_in[13];
    const float* g1b = (const float*)d_in[14];
    const float* be1b= (const float*)d_in[15];
    const float* wq2 = (const float*)d_in[16];
    const float* wk2 = (const float*)d_in[17];
    const float* wv2 = (const float*)d_in[18];
    const float* wo2 = (const float*)d_in[19];
    const float* bo2 = (const float*)d_in[20];
    const float* w2a = (const float*)d_in[21];
    const float* b2a = (const float*)d_in[22];
    const float* w2b = (const float*)d_in[23];
    const float* b2b = (const float*)d_in[24];
    const float* g2a = (const float*)d_in[25];
    const float* be2a= (const float*)d_in[26];
    const float* g2b = (const float*)d_in[27];
    const float* be2b= (const float*)d_in[28];
    const float* w4  = (const float*)d_in[29];
    const float* b4  = (const float*)d_in[30];

    int N = in_sizes[0] / D;

    float *Q1, *K1, *V1, *K2, *V2, *Q2, *ATT, *XA, *XB, *H, *RS;
    cudaGetSymbolAddress((void**)&Q1,  g_Q1);
    cudaGetSymbolAddress((void**)&K1,  g_K1);
    cudaGetSymbolAddress((void**)&V1,  g_V1);
    cudaGetSymbolAddress((void**)&K2,  g_K2);
    cudaGetSymbolAddress((void**)&V2,  g_V2);
    cudaGetSymbolAddress((void**)&Q2,  g_Q2);
    cudaGetSymbolAddress((void**)&ATT, g_ATT);
    cudaGetSymbolAddress((void**)&XA,  g_XA);
    cudaGetSymbolAddress((void**)&XB,  g_XB);
    cudaGetSymbolAddress((void**)&H,   g_H);
    cudaGetSymbolAddress((void**)&RS,  g_rs);

    int MB  = (N + 127) / 128;
    int WPB = (N + 7) / 8;  // warp-per-node kernels, 8 warps/block

    detect_valid_kernel<<<1, 1024>>>((const unsigned char*)valid, N * KNBR);
    rowsum_kernel<<<WPB, 256>>>(feat, RS, N);

    // ---- projections from feat (no bias) ----
    gemm_mma<0><<<dim3(MB, 1), 256>>>(feat, wq1, nullptr, nullptr, nullptr, nullptr, Q1, N, D, D);
    gemm_mma<0><<<dim3(MB, 1), 256>>>(feat, wk1, nullptr, nullptr, nullptr, nullptr, K1, N, D, D);
    gemm_mma<0><<<dim3(MB, 1), 256>>>(feat, wv1, nullptr, nullptr, nullptr, nullptr, V1, N, D, D);
    gemm_mma<0><<<dim3(MB, 1), 256>>>(feat, wk2, nullptr, nullptr, nullptr, nullptr, K2, N, D, D);
    gemm_mma<0><<<dim3(MB, 1), 256>>>(feat, wv2, nullptr, nullptr, nullptr, nullptr, V2, N, D, D);

    // ---- layer 1 ----
    attn_kernel<<<WPB, 256>>>(Q1, K1, V1, nbr, valid, RS, ATT, N);
    gemm_mma<3><<<dim3(MB, 1), 256>>>(ATT, wo1, bo1, feat, g1a, be1a, XA, N, D, D);       // XA = LN(feat + att@wo1)
    gemm_mma<1><<<dim3(MB, 2), 256>>>(XA, w1a, b1a, nullptr, nullptr, nullptr, H, N, D, 2 * D);
    gemm_mma<3><<<dim3(MB, 1), 256>>>(H, w1b, b1b, XA, g1b, be1b, XB, N, 2 * D, D);       // XB = LN(XA + H@w1b)

    // ---- layer 2 ----
    gemm_mma<0><<<dim3(MB, 1), 256>>>(XB, wq2, nullptr, nullptr, nullptr, nullptr, Q2, N, D, D);
    attn_kernel<<<WPB, 256>>>(Q2, K2, V2, nbr, valid, RS, ATT, N);
    gemm_mma<3><<<dim3(MB, 1), 256>>>(ATT, wo2, bo2, XB, g2a, be2a, XA, N, D, D);
    gemm_mma<1><<<dim3(MB, 2), 256>>>(XA, w2a, b2a, nullptr, nullptr, nullptr, H, N, D, 2 * D);
    gemm_mma<3><<<dim3(MB, 1), 256>>>(H, w2b, b2b, XA, g2b, be2b, XB, N, 2 * D, D);

    // ---- head: tanh(XB @ w4 + b4), Ncols = 64 ----
    gemm_mma<2><<<dim3(MB, 1), 256>>>(XB, w4, b4, nullptr, nullptr, nullptr, (float*)d_out, N, D, D / 2);
}

// round 5
// speedup vs baseline: 3.0625x; 1.3586x over previous
#include <cuda_runtime.h>
#include <math.h>

#define D 128
#define KNBR 5
#define NMAX 300000

// ---------------- scratch (static device memory; no allocations allowed) ----
__device__ float g_Q1[(size_t)NMAX * D];
__device__ float g_K1[(size_t)NMAX * D];
__device__ float g_V1[(size_t)NMAX * D];
__device__ float g_K2[(size_t)NMAX * D];
__device__ float g_V2[(size_t)NMAX * D];
__device__ float g_Q2[(size_t)NMAX * D];
__device__ float g_ATT[(size_t)NMAX * D];
__device__ float g_XA[(size_t)NMAX * D];
__device__ float g_XB[(size_t)NMAX * D];
__device__ float g_H[(size_t)NMAX * 2 * D];
__device__ float g_rs[NMAX];
__device__ int   g_validbyte;

// ---------------- detect whether nbr_valid is byte-bool or int32 ------------
__global__ void detect_valid_kernel(const unsigned char* __restrict__ p, int nelem) {
    if (threadIdx.x == 0) g_validbyte = 0;
    __syncthreads();
    int lim = nelem < 4096 ? nelem : 4096;
    int found = 0;
    for (int j = threadIdx.x; j < lim; j += blockDim.x)
        if ((j & 3) && p[j]) found = 1;
    if (found) g_validbyte = 1;
}

// ---------------- tf32 / mma / cp.async helpers ------------------------------
__device__ __forceinline__ unsigned f2tf32(float f) {
    unsigned u;
    asm("cvt.rna.tf32.f32 %0, %1;" : "=r"(u) : "f"(f));
    return u;
}

__device__ __forceinline__ void mma_tf32(float* c, const unsigned* a, const unsigned* b) {
    asm volatile(
        "mma.sync.aligned.m16n8k8.row.col.f32.tf32.tf32.f32 "
        "{%0,%1,%2,%3}, {%4,%5,%6,%7}, {%8,%9}, {%0,%1,%2,%3};"
        : "+f"(c[0]), "+f"(c[1]), "+f"(c[2]), "+f"(c[3])
        : "r"(a[0]), "r"(a[1]), "r"(a[2]), "r"(a[3]), "r"(b[0]), "r"(b[1]));
}

__device__ __forceinline__ void cp16(float* dst, const float* src, bool pred) {
    unsigned sa = (unsigned)__cvta_generic_to_shared(dst);
    int sz = pred ? 16 : 0;
    asm volatile("cp.async.cg.shared.global [%0], [%1], 16, %2;"
                 :: "r"(sa), "l"(src), "r"(sz) : "memory");
}
#define CP_COMMIT asm volatile("cp.async.commit_group;" ::: "memory")
__device__ __forceinline__ void cp_wait1() { asm volatile("cp.async.wait_group 1;" ::: "memory"); }
__device__ __forceinline__ void cp_wait0() { asm volatile("cp.async.wait_group 0;" ::: "memory"); }

// ---------------- fragment compute over one 16-k stage -----------------------
// Asm: [128][20] floats (row-major, pad 20).  Bsm: [16][136] floats.
// Both layouts are conflict-free for the m16n8k8 fragment pattern.
__device__ __forceinline__ void compute_stage(
    const float* __restrict__ Asm, const float* __restrict__ Bsm,
    int lane, int mrow, int ncol, float (&c)[2][8][4])
{
    #pragma unroll
    for (int ks = 0; ks < 16; ks += 8) {
        int kq = ks + (lane & 3);
        unsigned a[2][4], b[8][2];
        #pragma unroll
        for (int mt = 0; mt < 2; mt++) {
            int row = mrow + mt * 16 + (lane >> 2);
            a[mt][0] = f2tf32(Asm[row * 20 + kq]);
            a[mt][1] = f2tf32(Asm[(row + 8) * 20 + kq]);
            a[mt][2] = f2tf32(Asm[row * 20 + kq + 4]);
            a[mt][3] = f2tf32(Asm[(row + 8) * 20 + kq + 4]);
        }
        #pragma unroll
        for (int nt = 0; nt < 8; nt++) {
            int col = ncol + nt * 8 + (lane >> 2);
            b[nt][0] = f2tf32(Bsm[kq * 136 + col]);
            b[nt][1] = f2tf32(Bsm[(kq + 4) * 136 + col]);
        }
        #pragma unroll
        for (int mt = 0; mt < 2; mt++)
            #pragma unroll
            for (int nt = 0; nt < 8; nt++)
                mma_tf32(c[mt][nt], a[mt], b[nt]);
    }
}

// ---------------- pipelined GEMM, 128x128 tile, 256 threads ------------------
// EPI: 0 = bias(optional), 1 = bias+relu, 2 = bias+tanh, 3 = bias+res+LN (Ncols==128)
template <int EPI>
__global__ void __launch_bounds__(256, 2) gemm_mma(
    const float* __restrict__ X, const float* __restrict__ W,
    const float* __restrict__ bias, const float* __restrict__ res,
    const float* __restrict__ gam, const float* __restrict__ bet,
    float* __restrict__ Y, int M, int Kd, int Ncols)
{
    __shared__ float As[2][128][20];
    __shared__ float Bs[2][16][136];
    int row0 = blockIdx.x * 128;
    int col0 = blockIdx.y * 128;
    int tid = threadIdx.x, lane = tid & 31, warp = tid >> 5;
    int mrow = (warp >> 1) * 32, ncol = (warp & 1) * 64;

    // staging coords
    int s_arow = tid >> 1;                 // A: 1 row per 2 threads
    int s_aseg = (tid & 1) * 2;            // two consecutive 16B segs
    bool s_aok = (row0 + s_arow) < M;
    int s_bk = tid >> 4;                   // B: k row
    int s_bc = (tid & 15) * 8;             // col base (floats)

    float c[2][8][4] = {};
    int NIT = Kd >> 4;

    // prefetch stage 0
    {
        const float* sa = X + (size_t)(row0 + s_arow) * Kd + s_aseg * 4;
        cp16(&As[0][s_arow][s_aseg * 4],     s_aok ? sa     : X, s_aok);
        cp16(&As[0][s_arow][s_aseg * 4 + 4], s_aok ? sa + 4 : X, s_aok);
        const float* sb = W + (size_t)s_bk * Ncols + col0 + s_bc;
        bool p0 = (col0 + s_bc) < Ncols, p1 = (col0 + s_bc + 4) < Ncols;
        cp16(&Bs[0][s_bk][s_bc],     p0 ? sb     : W, p0);
        cp16(&Bs[0][s_bk][s_bc + 4], p1 ? sb + 4 : W, p1);
        CP_COMMIT;
    }

    for (int it = 0; it < NIT; it++) {
        if (it + 1 < NIT) {
            int st = (it + 1) & 1, k0 = (it + 1) * 16;
            const float* sa = X + (size_t)(row0 + s_arow) * Kd + k0 + s_aseg * 4;
            cp16(&As[st][s_arow][s_aseg * 4],     s_aok ? sa     : X, s_aok);
            cp16(&As[st][s_arow][s_aseg * 4 + 4], s_aok ? sa + 4 : X, s_aok);
            const float* sb = W + (size_t)(k0 + s_bk) * Ncols + col0 + s_bc;
            bool p0 = (col0 + s_bc) < Ncols, p1 = (col0 + s_bc + 4) < Ncols;
            cp16(&Bs[st][s_bk][s_bc],     p0 ? sb     : W, p0);
            cp16(&Bs[st][s_bk][s_bc + 4], p1 ? sb + 4 : W, p1);
            CP_COMMIT;
            cp_wait1();
        } else {
            cp_wait0();
        }
        __syncthreads();
        compute_stage(&As[it & 1][0][0], &Bs[it & 1][0][0], lane, mrow, ncol, c);
        __syncthreads();
    }

    if (EPI != 3) {
        const bool hasb = (bias != nullptr);
        #pragma unroll
        for (int mt = 0; mt < 2; mt++)
            #pragma unroll
            for (int nt = 0; nt < 8; nt++) {
                int col = col0 + ncol + nt * 8 + (lane & 3) * 2;
                if (col >= Ncols) continue;
                float bx = 0.f, by = 0.f;
                if (hasb) { float2 bb = *(const float2*)&bias[col]; bx = bb.x; by = bb.y; }
                #pragma unroll
                for (int rh = 0; rh < 2; rh++) {
                    int row = row0 + mrow + mt * 16 + rh * 8 + (lane >> 2);
                    if (row >= M) continue;
                    float x0 = c[mt][nt][rh * 2 + 0] + bx;
                    float x1 = c[mt][nt][rh * 2 + 1] + by;
                    if (EPI == 1) { x0 = fmaxf(x0, 0.f); x1 = fmaxf(x1, 0.f); }
                    if (EPI == 2) { x0 = tanhf(x0); x1 = tanhf(x1); }
                    *(float2*)&Y[(size_t)row * Ncols + col] = make_float2(x0, x1);
                }
            }
    } else {
        // LayerNorm epilogue (Ncols == 128, col0 == 0)
        float2* red = (float2*)&As[0][0][0];      // 128 rows x 2 warp-cols
        int warpN = warp & 1;
        #pragma unroll
        for (int mt = 0; mt < 2; mt++)
            #pragma unroll
            for (int rh = 0; rh < 2; rh++) {
                int rl  = mrow + mt * 16 + rh * 8 + (lane >> 2);
                int row = row0 + rl;
                bool ok = row < M;
                float s = 0.f, sq = 0.f;
                #pragma unroll
                for (int nt = 0; nt < 8; nt++) {
                    int col = ncol + nt * 8 + (lane & 3) * 2;
                    float2 rr = ok ? *(const float2*)&res[(size_t)row * 128 + col]
                                   : make_float2(0.f, 0.f);
                    float2 bb = *(const float2*)&bias[col];
                    float x0 = c[mt][nt][rh * 2 + 0] + rr.x + bb.x;
                    float x1 = c[mt][nt][rh * 2 + 1] + rr.y + bb.y;
                    c[mt][nt][rh * 2 + 0] = x0;
                    c[mt][nt][rh * 2 + 1] = x1;
                    s += x0 + x1;
                    sq += x0 * x0 + x1 * x1;
                }
                s  += __shfl_xor_sync(0xffffffffu, s, 1);
                s  += __shfl_xor_sync(0xffffffffu, s, 2);
                sq += __shfl_xor_sync(0xffffffffu, sq, 1);
                sq += __shfl_xor_sync(0xffffffffu, sq, 2);
                if ((lane & 3) == 0) red[rl * 2 + warpN] = make_float2(s, sq);
            }
        __syncthreads();
        #pragma unroll
        for (int mt = 0; mt < 2; mt++)
            #pragma unroll
            for (int rh = 0; rh < 2; rh++) {
                int rl  = mrow + mt * 16 + rh * 8 + (lane >> 2);
                int row = row0 + rl;
                float2 e0 = red[rl * 2 + 0];
                float2 e1 = red[rl * 2 + 1];
                float s = e0.x + e1.x, sq = e0.y + e1.y;
                float mean = s * (1.f / 128.f);
                float var  = sq * (1.f / 128.f) - mean * mean;
                float rstd = rsqrtf(var + 1e-5f);
                if (row < M) {
                    #pragma unroll
                    for (int nt = 0; nt < 8; nt++) {
                        int col = ncol + nt * 8 + (lane & 3) * 2;
                        float2 gg = *(const float2*)&gam[col];
                        float2 ee = *(const float2*)&bet[col];
                        float2 o;
                        o.x = (c[mt][nt][rh * 2 + 0] - mean) * rstd * gg.x + ee.x;
                        o.y = (c[mt][nt][rh * 2 + 1] - mean) * rstd * gg.y + ee.y;
                        *(float2*)&Y[(size_t)row * 128 + col] = o;
                    }
                }
            }
    }
}

// ---------------- fused 5-projection kernel (A resident, B streamed) ---------
// Dynamic smem: Af[8][128][20] (80KB) + Bs[2][16][136] (17KB).  1 CTA/SM.
// Also computes per-node rowsum (mask) from the resident A tile.
struct Proj5 { const float* W[5]; float* Y[5]; };

__global__ void __launch_bounds__(256, 1) proj5_kernel(
    const float* __restrict__ X, Proj5 p, float* __restrict__ rs, int M)
{
    extern __shared__ float sm[];
    float (*Af)[128][20] = (float(*)[128][20])sm;
    float (*Bs)[16][136] = (float(*)[16][136])(sm + 8 * 128 * 20);
    int row0 = blockIdx.x * 128;
    int tid = threadIdx.x, lane = tid & 31, warp = tid >> 5;
    int mrow = (warp >> 1) * 32, ncol = (warp & 1) * 64;

    // load full A tile (8 k-chunks)
    {
        int row = tid >> 1;
        int seg = (tid & 1) * 2;
        bool ok = (row0 + row) < M;
        #pragma unroll
        for (int kc = 0; kc < 8; kc++) {
            const float* sa = X + (size_t)(row0 + row) * 128 + kc * 16 + seg * 4;
            cp16(&Af[kc][row][seg * 4],     ok ? sa     : X, ok);
            cp16(&Af[kc][row][seg * 4 + 4], ok ? sa + 4 : X, ok);
        }
        CP_COMMIT;
    }
    int s_bk = tid >> 4;
    int s_bc = (tid & 15) * 8;
    // prefetch B(p=0, kc=0)
    {
        const float* sb = p.W[0] + (size_t)s_bk * 128 + s_bc;
        cp16(&Bs[0][s_bk][s_bc],     sb,     true);
        cp16(&Bs[0][s_bk][s_bc + 4], sb + 4, true);
        CP_COMMIT;
    }

    float c[2][8][4] = {};
    for (int it = 0; it < 40; it++) {
        int kc = it & 7;
        if (it + 1 < 40) {
            int st = (it + 1) & 1;
            const float* Wn = p.W[(it + 1) >> 3];
            int k0 = ((it + 1) & 7) * 16;
            const float* sb = Wn + (size_t)(k0 + s_bk) * 128 + s_bc;
            cp16(&Bs[st][s_bk][s_bc],     sb,     true);
            cp16(&Bs[st][s_bk][s_bc + 4], sb + 4, true);
            CP_COMMIT;
            cp_wait1();
        } else {
            cp_wait0();
        }
        __syncthreads();
        if (it == 0) {
            // rowsum for the mask, from the resident A tile
            int row = tid >> 1, half = tid & 1;
            float s = 0.f;
            #pragma unroll
            for (int q = 0; q < 4; q++) {
                int kcc = half * 4 + q;
                #pragma unroll
                for (int kl = 0; kl < 16; kl++) s += Af[kcc][row][kl];
            }
            s += __shfl_xor_sync(0xffffffffu, s, 1);
            if (half == 0 && row0 + row < M) rs[row0 + row] = s;
        }
        compute_stage(&Af[kc][0][0], &Bs[it & 1][0][0], lane, mrow, ncol, c);
        __syncthreads();
        if (kc == 7) {
            float* Y = p.Y[it >> 3];
            #pragma unroll
            for (int mt = 0; mt < 2; mt++)
                #pragma unroll
                for (int nt = 0; nt < 8; nt++) {
                    int col = ncol + nt * 8 + (lane & 3) * 2;
                    #pragma unroll
                    for (int rh = 0; rh < 2; rh++) {
                        int row = row0 + mrow + mt * 16 + rh * 8 + (lane >> 2);
                        if (row < M)
                            *(float2*)&Y[(size_t)row * 128 + col] =
                                make_float2(c[mt][nt][rh * 2 + 0], c[mt][nt][rh * 2 + 1]);
                        c[mt][nt][rh * 2 + 0] = 0.f;
                        c[mt][nt][rh * 2 + 1] = 0.f;
                    }
                }
        }
    }
}

// ---------------- warp-per-node attention (82% of HBM; unchanged) ------------
__global__ void attn_kernel(const float* __restrict__ Q, const float* __restrict__ Kp,
                            const float* __restrict__ Vp, const int* __restrict__ nbr,
                            const void* __restrict__ validp, const float* __restrict__ rs,
                            float* __restrict__ out, int N) {
    int warp = (blockIdx.x * blockDim.x + threadIdx.x) >> 5;
    int lane = threadIdx.x & 31;
    if (warp >= N) return;
    int i = warp;
    float4 q = ((const float4*)Q)[(size_t)i * 32 + lane];
    bool isbyte = (g_validbyte != 0);
    float d[KNBR];
    float4 v[KNBR];
    #pragma unroll
    for (int j = 0; j < KNBR; j++) {
        int nb = nbr[(size_t)i * KNBR + j];
        int vld = isbyte ? (int)((const unsigned char*)validp)[(size_t)i * KNBR + j]
                         : ((const int*)validp)[(size_t)i * KNBR + j];
        bool masked = (vld == 0) || (rs[nb] == 0.0f);
        float4 k4 = ((const float4*)Kp)[(size_t)nb * 32 + lane];
        v[j]      = ((const float4*)Vp)[(size_t)nb * 32 + lane];
        float p = q.x * k4.x + q.y * k4.y + q.z * k4.z + q.w * k4.w;
        p += __shfl_xor_sync(0xffffffffu, p, 1);
        p += __shfl_xor_sync(0xffffffffu, p, 2);
        d[j] = masked ? -1e30f : p * 0.25f;   // dh^-0.5 = 1/4
    }
    float m = d[0];
    #pragma unroll
    for (int j = 1; j < KNBR; j++) m = fmaxf(m, d[j]);
    float e[KNBR], s = 0.f;
    #pragma unroll
    for (int j = 0; j < KNBR; j++) { e[j] = __expf(d[j] - m); s += e[j]; }
    float inv = 1.f / s;
    float4 o = make_float4(0.f, 0.f, 0.f, 0.f);
    #pragma unroll
    for (int j = 0; j < KNBR; j++) {
        float a = e[j] * inv;
        o.x += a * v[j].x; o.y += a * v[j].y; o.z += a * v[j].z; o.w += a * v[j].w;
    }
    ((float4*)out)[(size_t)i * 32 + lane] = o;
}

// ---------------- host orchestration ----------------------------------------
extern "C" void kernel_launch(void* const* d_in, const int* in_sizes, int n_in,
                              void* d_out, int out_size) {
    const float* feat  = (const float*)d_in[0];
    const int*   nbr   = (const int*)d_in[1];
    const void*  valid = d_in[2];
    const float* wq1 = (const float*)d_in[3];
    const float* wk1 = (const float*)d_in[4];
    const float* wv1 = (const float*)d_in[5];
    const float* wo1 = (const float*)d_in[6];
    const float* bo1 = (const float*)d_in[7];
    const float* w1a = (const float*)d_in[8];
    const float* b1a = (const float*)d_in[9];
    const float* w1b = (const float*)d_in[10];
    const float* b1b = (const float*)d_in[11];
    const float* g1a = (const float*)d_in[12];
    const float* be1a= (const float*)d_in[13];
    const float* g1b = (const float*)d_in[14];
    const float* be1b= (const float*)d_in[15];
    const float* wq2 = (const float*)d_in[16];
    const float* wk2 = (const float*)d_in[17];
    const float* wv2 = (const float*)d_in[18];
    const float* wo2 = (const float*)d_in[19];
    const float* bo2 = (const float*)d_in[20];
    const float* w2a = (const float*)d_in[21];
    const float* b2a = (const float*)d_in[22];
    const float* w2b = (const float*)d_in[23];
    const float* b2b = (const float*)d_in[24];
    const float* g2a = (const float*)d_in[25];
    const float* be2a= (const float*)d_in[26];
    const float* g2b = (const float*)d_in[27];
    const float* be2b= (const float*)d_in[28];
    const float* w4  = (const float*)d_in[29];
    const float* b4  = (const float*)d_in[30];

    int N = in_sizes[0] / D;

    float *Q1, *K1, *V1, *K2, *V2, *Q2, *ATT, *XA, *XB, *H, *RS;
    cudaGetSymbolAddress((void**)&Q1,  g_Q1);
    cudaGetSymbolAddress((void**)&K1,  g_K1);
    cudaGetSymbolAddress((void**)&V1,  g_V1);
    cudaGetSymbolAddress((void**)&K2,  g_K2);
    cudaGetSymbolAddress((void**)&V2,  g_V2);
    cudaGetSymbolAddress((void**)&Q2,  g_Q2);
    cudaGetSymbolAddress((void**)&ATT, g_ATT);
    cudaGetSymbolAddress((void**)&XA,  g_XA);
    cudaGetSymbolAddress((void**)&XB,  g_XB);
    cudaGetSymbolAddress((void**)&H,   g_H);
    cudaGetSymbolAddress((void**)&RS,  g_rs);

    int MB  = (N + 127) / 128;
    int WPB = (N + 7) / 8;  // warp-per-node kernels, 8 warps/block

    const int PROJ_SMEM = (8 * 128 * 20 + 2 * 16 * 136) * 4;  // 99328 B
    cudaFuncSetAttribute(proj5_kernel, cudaFuncAttributeMaxDynamicSharedMemorySize, PROJ_SMEM);

    detect_valid_kernel<<<1, 1024>>>((const unsigned char*)valid, N * KNBR);

    // ---- fused 5-way projection (also writes rowsum mask) ----
    Proj5 p;
    p.W[0] = wq1; p.W[1] = wk1; p.W[2] = wv1; p.W[3] = wk2; p.W[4] = wv2;
    p.Y[0] = Q1;  p.Y[1] = K1;  p.Y[2] = V1;  p.Y[3] = K2;  p.Y[4] = V2;
    proj5_kernel<<<MB, 256, PROJ_SMEM>>>(feat, p, RS, N);

    // ---- layer 1 ----
    attn_kernel<<<WPB, 256>>>(Q1, K1, V1, nbr, valid, RS, ATT, N);
    gemm_mma<3><<<dim3(MB, 1), 256>>>(ATT, wo1, bo1, feat, g1a, be1a, XA, N, D, D);
    gemm_mma<1><<<dim3(MB, 2), 256>>>(XA, w1a, b1a, nullptr, nullptr, nullptr, H, N, D, 2 * D);
    gemm_mma<3><<<dim3(MB, 1), 256>>>(H, w1b, b1b, XA, g1b, be1b, XB, N, 2 * D, D);

    // ---- layer 2 ----
    gemm_mma<0><<<dim3(MB, 1), 256>>>(XB, wq2, nullptr, nullptr, nullptr, nullptr, Q2, N, D, D);
    attn_kernel<<<WPB, 256>>>(Q2, K2, V2, nbr, valid, RS, ATT, N);
    gemm_mma<3><<<dim3(MB, 1), 256>>>(ATT, wo2, bo2, XB, g2a, be2a, XA, N, D, D);
    gemm_mma<1><<<dim3(MB, 2), 256>>>(XA, w2a, b2a, nullptr, nullptr, nullptr, H, N, D, 2 * D);
    gemm_mma<3><<<dim3(MB, 1), 256>>>(H, w2b, b2b, XA, g2b, be2b, XB, N, 2 * D, D);

    // ---- head: tanh(XB @ w4 + b4), Ncols = 64 ----
    gemm_mma<2><<<dim3(MB, 1), 256>>>(XB, w4, b4, nullptr, nullptr, nullptr, (float*)d_out, N, D, D / 2);
}

// round 6
// speedup vs baseline: 3.0830x; 1.0067x over previous
#include <cuda_runtime.h>
#include <math.h>

#define D 128
#define KNBR 5
#define NMAX 300000

// ---------------- scratch (static device memory; no allocations allowed) ----
__device__ float g_Q1[(size_t)NMAX * D];
__device__ float g_K1[(size_t)NMAX * D];
__device__ float g_V1[(size_t)NMAX * D];
__device__ float g_K2[(size_t)NMAX * D];
__device__ float g_V2[(size_t)NMAX * D];
__device__ float g_Q2[(size_t)NMAX * D];
__device__ float g_ATT[(size_t)NMAX * D];
__device__ float g_XB[(size_t)NMAX * D];
__device__ float g_rs[NMAX];
__device__ int   g_validbyte;

// ---------------- detect whether nbr_valid is byte-bool or int32 ------------
__global__ void detect_valid_kernel(const unsigned char* __restrict__ p, int nelem) {
    if (threadIdx.x == 0) g_validbyte = 0;
    __syncthreads();
    int lim = nelem < 4096 ? nelem : 4096;
    int found = 0;
    for (int j = threadIdx.x; j < lim; j += blockDim.x)
        if ((j & 3) && p[j]) found = 1;
    if (found) g_validbyte = 1;
}

// ---------------- tf32 / mma / cp.async helpers ------------------------------
__device__ __forceinline__ unsigned f2tf32(float f) {
    unsigned u;
    asm("cvt.rna.tf32.f32 %0, %1;" : "=r"(u) : "f"(f));
    return u;
}

__device__ __forceinline__ void mma_tf32(float* c, const unsigned* a, const unsigned* b) {
    asm volatile(
        "mma.sync.aligned.m16n8k8.row.col.f32.tf32.tf32.f32 "
        "{%0,%1,%2,%3}, {%4,%5,%6,%7}, {%8,%9}, {%0,%1,%2,%3};"
        : "+f"(c[0]), "+f"(c[1]), "+f"(c[2]), "+f"(c[3])
        : "r"(a[0]), "r"(a[1]), "r"(a[2]), "r"(a[3]), "r"(b[0]), "r"(b[1]));
}

__device__ __forceinline__ void cp16(float* dst, const float* src, bool pred) {
    unsigned sa = (unsigned)__cvta_generic_to_shared(dst);
    int sz = pred ? 16 : 0;
    asm volatile("cp.async.cg.shared.global [%0], [%1], 16, %2;"
                 :: "r"(sa), "l"(src), "r"(sz) : "memory");
}
#define CP_COMMIT asm volatile("cp.async.commit_group;" ::: "memory")
__device__ __forceinline__ void cp_wait1() { asm volatile("cp.async.wait_group 1;" ::: "memory"); }
__device__ __forceinline__ void cp_wait0() { asm volatile("cp.async.wait_group 0;" ::: "memory"); }

// ============================================================================
//  Generic fragment compute: A in [128][20] chunk, B in [16][136] stage.
//  Warp tile 32 x (NT*8).
// ============================================================================
template <int NT>
__device__ __forceinline__ void compute_stageN(
    const float* __restrict__ Asm, const float* __restrict__ Bsm,
    int lane, int mrow, int ncol, float (&c)[2][NT][4])
{
    #pragma unroll
    for (int ks = 0; ks < 16; ks += 8) {
        int kq = ks + (lane & 3);
        unsigned a[2][4], b[NT][2];
        #pragma unroll
        for (int mt = 0; mt < 2; mt++) {
            int row = mrow + mt * 16 + (lane >> 2);
            a[mt][0] = f2tf32(Asm[row * 20 + kq]);
            a[mt][1] = f2tf32(Asm[(row + 8) * 20 + kq]);
            a[mt][2] = f2tf32(Asm[row * 20 + kq + 4]);
            a[mt][3] = f2tf32(Asm[(row + 8) * 20 + kq + 4]);
        }
        #pragma unroll
        for (int nt = 0; nt < NT; nt++) {
            int col = ncol + nt * 8 + (lane >> 2);
            b[nt][0] = f2tf32(Bsm[kq * 136 + col]);
            b[nt][1] = f2tf32(Bsm[(kq + 4) * 136 + col]);
        }
        #pragma unroll
        for (int mt = 0; mt < 2; mt++)
            #pragma unroll
            for (int nt = 0; nt < NT; nt++)
                mma_tf32(c[mt][nt], a[mt], b[nt]);
    }
}

// Stream B (K=128, 8 stages) against a resident A region [8][128][20].
template <int NT>
__device__ __forceinline__ void gemm_stream(
    const float* __restrict__ Areg, const float* __restrict__ W,
    int pitch, int colOff, float* __restrict__ Bsm,
    int tid, int lane, int mrow, int ncol, float (&c)[2][NT][4])
{
    constexpr int PERK = NT * 8;          // cp16 ops per B k-row
    int bk = tid / PERK, bc = (tid % PERK) * 4;
    bool act = tid < 16 * PERK;
    if (act) cp16(&Bsm[bk * 136 + bc], W + (size_t)bk * pitch + colOff + bc, true);
    CP_COMMIT;
    for (int it = 0; it < 8; it++) {
        if (it < 7) {
            int st = (it + 1) & 1, k0 = (it + 1) * 16;
            if (act) cp16(&Bsm[st * 2176 + bk * 136 + bc],
                          W + (size_t)(k0 + bk) * pitch + colOff + bc, true);
            CP_COMMIT;
            cp_wait1();
        } else {
            cp_wait0();
        }
        __syncthreads();
        compute_stageN<NT>(Areg + it * 2560, Bsm + (it & 1) * 2176, lane, mrow, ncol, c);
        __syncthreads();
    }
}

// bias + residual (global or smem A-layout) + LayerNorm; output to smem
// A-layout and/or global. Overwrites c with pre-LN values.
__device__ __forceinline__ void ln_epi(
    float (&c)[2][4][4], const float* __restrict__ bias,
    const float* __restrict__ resg, const float* __restrict__ ressm,
    const float* __restrict__ gam, const float* __restrict__ bet,
    float2* __restrict__ red, float* __restrict__ outsm, float* __restrict__ outg,
    int row0, int M, int lane, int warp, int mrow, int ncol)
{
    int warpN = warp & 3;
    #pragma unroll
    for (int mt = 0; mt < 2; mt++)
        #pragma unroll
        for (int rh = 0; rh < 2; rh++) {
            int rl = mrow + mt * 16 + rh * 8 + (lane >> 2);
            bool ok = row0 + rl < M;
            float s = 0.f, sq = 0.f;
            #pragma unroll
            for (int nt = 0; nt < 4; nt++) {
                int col = ncol + nt * 8 + (lane & 3) * 2;
                float2 rr;
                if (ressm) rr = *(const float2*)&ressm[(col >> 4) * 2560 + rl * 20 + (col & 15)];
                else rr = ok ? *(const float2*)&resg[(size_t)(row0 + rl) * 128 + col]
                             : make_float2(0.f, 0.f);
                float2 bb = *(const float2*)&bias[col];
                float x0 = c[mt][nt][rh * 2 + 0] + rr.x + bb.x;
                float x1 = c[mt][nt][rh * 2 + 1] + rr.y + bb.y;
                c[mt][nt][rh * 2 + 0] = x0;
                c[mt][nt][rh * 2 + 1] = x1;
                s += x0 + x1;
                sq += x0 * x0 + x1 * x1;
            }
            s  += __shfl_xor_sync(0xffffffffu, s, 1);
            s  += __shfl_xor_sync(0xffffffffu, s, 2);
            sq += __shfl_xor_sync(0xffffffffu, sq, 1);
            sq += __shfl_xor_sync(0xffffffffu, sq, 2);
            if ((lane & 3) == 0) red[rl * 4 + warpN] = make_float2(s, sq);
        }
    __syncthreads();
    #pragma unroll
    for (int mt = 0; mt < 2; mt++)
        #pragma unroll
        for (int rh = 0; rh < 2; rh++) {
            int rl = mrow + mt * 16 + rh * 8 + (lane >> 2);
            float s = 0.f, sq = 0.f;
            #pragma unroll
            for (int wN = 0; wN < 4; wN++) { float2 e = red[rl * 4 + wN]; s += e.x; sq += e.y; }
            float mean = s * (1.f / 128.f);
            float var  = sq * (1.f / 128.f) - mean * mean;
            float rstd = rsqrtf(var + 1e-5f);
            bool ok = row0 + rl < M;
            #pragma unroll
            for (int nt = 0; nt < 4; nt++) {
                int col = ncol + nt * 8 + (lane & 3) * 2;
                float2 gg = *(const float2*)&gam[col];
                float2 ee = *(const float2*)&bet[col];
                float2 o;
                o.x = (c[mt][nt][rh * 2 + 0] - mean) * rstd * gg.x + ee.x;
                o.y = (c[mt][nt][rh * 2 + 1] - mean) * rstd * gg.y + ee.y;
                if (outsm) *(float2*)&outsm[(col >> 4) * 2560 + rl * 20 + (col & 15)] = o;
                if (outg && ok) *(float2*)&outg[(size_t)(row0 + rl) * 128 + col] = o;
            }
        }
    __syncthreads();
}

// relu(c + bias) -> smem A-layout; zeros c for reuse.
__device__ __forceinline__ void store_relu_sm(
    float (&c)[2][4][4], const float* __restrict__ bias, float* __restrict__ outsm,
    int lane, int mrow, int ncol)
{
    #pragma unroll
    for (int mt = 0; mt < 2; mt++)
        #pragma unroll
        for (int rh = 0; rh < 2; rh++) {
            int rl = mrow + mt * 16 + rh * 8 + (lane >> 2);
            #pragma unroll
            for (int nt = 0; nt < 4; nt++) {
                int col = ncol + nt * 8 + (lane & 3) * 2;
                float2 bb = *(const float2*)&bias[col];
                float2 o;
                o.x = fmaxf(c[mt][nt][rh * 2 + 0] + bb.x, 0.f);
                o.y = fmaxf(c[mt][nt][rh * 2 + 1] + bb.y, 0.f);
                *(float2*)&outsm[(col >> 4) * 2560 + rl * 20 + (col & 15)] = o;
                c[mt][nt][rh * 2 + 0] = 0.f;
                c[mt][nt][rh * 2 + 1] = 0.f;
            }
        }
}

// ============================================================================
//  Mega layer kernel: XA=LN(res+ATT@wo+bo); H=relu(XA@wa+ba);
//  XB=LN(XA+H@wb+bb); post: Yp = act(XB@Wp + bp). XA/H never leave the SM.
//  512 threads, 1 CTA/SM.  NP: post output cols. POSTTANH: tanh on post.
// ============================================================================
template <int NP, int WRITE_XB, int POSTTANH>
__global__ void __launch_bounds__(512, 1) layer_kernel(
    const float* __restrict__ ATT, const float* __restrict__ wo, const float* __restrict__ bo,
    const float* __restrict__ res, const float* __restrict__ ga, const float* __restrict__ bea,
    const float* __restrict__ wa, const float* __restrict__ ba,
    const float* __restrict__ wb, const float* __restrict__ bb,
    const float* __restrict__ gb, const float* __restrict__ beb,
    const float* __restrict__ Wp, const float* __restrict__ bp,
    float* __restrict__ XB, float* __restrict__ Yp, int M)
{
    extern __shared__ float sm[];
    float*  R1  = sm;                       // XA, [8][128][20]
    float*  R2  = R1 + 8 * 128 * 20;        // ATT / H-half / XB tile
    float*  Bsm = R2 + 8 * 128 * 20;        // [2][16][136]
    float2* red = (float2*)(Bsm + 2 * 16 * 136);  // [128][4]

    int row0 = blockIdx.x * 128;
    int tid = threadIdx.x, lane = tid & 31, warp = tid >> 5;
    int mrow = (warp >> 2) * 32;
    int ncol = (warp & 3) * 32;

    // stage ATT tile -> R2 (zero-filled beyond M)
    {
        int row = tid >> 2, seg = (tid & 3) * 4;
        bool ok = row0 + row < M;
        const float* src = ATT + (size_t)(row0 + row) * 128 + seg;
        #pragma unroll
        for (int kc = 0; kc < 8; kc++)
            cp16(&R2[kc * 2560 + row * 20 + seg], ok ? src + kc * 16 : ATT, ok);
        CP_COMMIT;
    }

    float cA[2][4][4] = {};
    float cB[2][4][4] = {};

    // P1: cA = ATT @ wo
    gemm_stream<4>(R2, wo, 128, 0, Bsm, tid, lane, mrow, ncol, cA);
    // P2: XA = LN(cA + bo + res) -> R1 (smem only)
    ln_epi(cA, bo, res, nullptr, ga, bea, red, R1, nullptr, row0, M, lane, warp, mrow, ncol);

    #pragma unroll
    for (int mt = 0; mt < 2; mt++)
        #pragma unroll
        for (int nt = 0; nt < 4; nt++)
            #pragma unroll
            for (int q = 0; q < 4; q++) cA[mt][nt][q] = 0.f;

    // FFN in two 128-col halves, H resident in R2
    #pragma unroll
    for (int h = 0; h < 2; h++) {
        gemm_stream<4>(R1, wa, 256, h * 128, Bsm, tid, lane, mrow, ncol, cA);
        store_relu_sm(cA, ba + h * 128, R2, lane, mrow, ncol);   // also zeros cA
        gemm_stream<4>(R2, wb + (size_t)h * 128 * 128, 128, 0, Bsm, tid, lane, mrow, ncol, cB);
    }

    // XB = LN(cB + bb + XA[smem]) -> R2 (for post) and optionally global
    ln_epi(cB, bb, nullptr, R1, gb, beb, red, R2, WRITE_XB ? XB : nullptr,
           row0, M, lane, warp, mrow, ncol);

    // post: Yp = act(XB @ Wp + bp)
    constexpr int NTP = NP / 32;
    int ncolp = (warp & 3) * (NTP * 8);
    float cP[2][NTP][4] = {};
    gemm_stream<NTP>(R2, Wp, NP, 0, Bsm, tid, lane, mrow, ncolp, cP);

    const bool hasb = (bp != nullptr);
    #pragma unroll
    for (int mt = 0; mt < 2; mt++)
        #pragma unroll
        for (int rh = 0; rh < 2; rh++) {
            int rl = mrow + mt * 16 + rh * 8 + (lane >> 2);
            if (row0 + rl >= M) continue;
            #pragma unroll
            for (int nt = 0; nt < NTP; nt++) {
                int col = ncolp + nt * 8 + (lane & 3) * 2;
                float bx = 0.f, by = 0.f;
                if (hasb) { float2 v = *(const float2*)&bp[col]; bx = v.x; by = v.y; }
                float x0 = cP[mt][nt][rh * 2 + 0] + bx;
                float x1 = cP[mt][nt][rh * 2 + 1] + by;
                if (POSTTANH) { x0 = tanhf(x0); x1 = tanhf(x1); }
                *(float2*)&Yp[(size_t)(row0 + rl) * NP + col] = make_float2(x0, x1);
            }
        }
}

// ---------------- proj5: fused 5-way projection, A resident (unchanged) -----
struct Proj5 { const float* W[5]; float* Y[5]; };

__device__ __forceinline__ void compute_stage(
    const float* __restrict__ Asm, const float* __restrict__ Bsm,
    int lane, int mrow, int ncol, float (&c)[2][8][4])
{
    #pragma unroll
    for (int ks = 0; ks < 16; ks += 8) {
        int kq = ks + (lane & 3);
        unsigned a[2][4], b[8][2];
        #pragma unroll
        for (int mt = 0; mt < 2; mt++) {
            int row = mrow + mt * 16 + (lane >> 2);
            a[mt][0] = f2tf32(Asm[row * 20 + kq]);
            a[mt][1] = f2tf32(Asm[(row + 8) * 20 + kq]);
            a[mt][2] = f2tf32(Asm[row * 20 + kq + 4]);
            a[mt][3] = f2tf32(Asm[(row + 8) * 20 + kq + 4]);
        }
        #pragma unroll
        for (int nt = 0; nt < 8; nt++) {
            int col = ncol + nt * 8 + (lane >> 2);
            b[nt][0] = f2tf32(Bsm[kq * 136 + col]);
            b[nt][1] = f2tf32(Bsm[(kq + 4) * 136 + col]);
        }
        #pragma unroll
        for (int mt = 0; mt < 2; mt++)
            #pragma unroll
            for (int nt = 0; nt < 8; nt++)
                mma_tf32(c[mt][nt], a[mt], b[nt]);
    }
}

__global__ void __launch_bounds__(256, 1) proj5_kernel(
    const float* __restrict__ X, Proj5 p, float* __restrict__ rs, int M)
{
    extern __shared__ float sm[];
    float (*Af)[128][20] = (float(*)[128][20])sm;
    float (*Bs)[16][136] = (float(*)[16][136])(sm + 8 * 128 * 20);
    int row0 = blockIdx.x * 128;
    int tid = threadIdx.x, lane = tid & 31, warp = tid >> 5;
    int mrow = (warp >> 1) * 32, ncol = (warp & 1) * 64;

    {
        int row = tid >> 1;
        int seg = (tid & 1) * 2;
        bool ok = (row0 + row) < M;
        #pragma unroll
        for (int kc = 0; kc < 8; kc++) {
            const float* sa = X + (size_t)(row0 + row) * 128 + kc * 16 + seg * 4;
            cp16(&Af[kc][row][seg * 4],     ok ? sa     : X, ok);
            cp16(&Af[kc][row][seg * 4 + 4], ok ? sa + 4 : X, ok);
        }
        CP_COMMIT;
    }
    int s_bk = tid >> 4;
    int s_bc = (tid & 15) * 8;
    {
        const float* sb = p.W[0] + (size_t)s_bk * 128 + s_bc;
        cp16(&Bs[0][s_bk][s_bc],     sb,     true);
        cp16(&Bs[0][s_bk][s_bc + 4], sb + 4, true);
        CP_COMMIT;
    }

    float c[2][8][4] = {};
    for (int it = 0; it < 40; it++) {
        int kc = it & 7;
        if (it + 1 < 40) {
            int st = (it + 1) & 1;
            const float* Wn = p.W[(it + 1) >> 3];
            int k0 = ((it + 1) & 7) * 16;
            const float* sb = Wn + (size_t)(k0 + s_bk) * 128 + s_bc;
            cp16(&Bs[st][s_bk][s_bc],     sb,     true);
            cp16(&Bs[st][s_bk][s_bc + 4], sb + 4, true);
            CP_COMMIT;
            cp_wait1();
        } else {
            cp_wait0();
        }
        __syncthreads();
        if (it == 0) {
            int row = tid >> 1, half = tid & 1;
            float s = 0.f;
            #pragma unroll
            for (int q = 0; q < 4; q++) {
                int kcc = half * 4 + q;
                #pragma unroll
                for (int kl = 0; kl < 16; kl++) s += Af[kcc][row][kl];
            }
            s += __shfl_xor_sync(0xffffffffu, s, 1);
            if (half == 0 && row0 + row < M) rs[row0 + row] = s;
        }
        compute_stage(&Af[kc][0][0], &Bs[it & 1][0][0], lane, mrow, ncol, c);
        __syncthreads();
        if (kc == 7) {
            float* Y = p.Y[it >> 3];
            #pragma unroll
            for (int mt = 0; mt < 2; mt++)
                #pragma unroll
                for (int nt = 0; nt < 8; nt++) {
                    int col = ncol + nt * 8 + (lane & 3) * 2;
                    #pragma unroll
                    for (int rh = 0; rh < 2; rh++) {
                        int row = row0 + mrow + mt * 16 + rh * 8 + (lane >> 2);
                        if (row < M)
                            *(float2*)&Y[(size_t)row * 128 + col] =
                                make_float2(c[mt][nt][rh * 2 + 0], c[mt][nt][rh * 2 + 1]);
                        c[mt][nt][rh * 2 + 0] = 0.f;
                        c[mt][nt][rh * 2 + 1] = 0.f;
                    }
                }
        }
    }
}

// ---------------- warp-per-node attention (82% of HBM; unchanged) ------------
__global__ void attn_kernel(const float* __restrict__ Q, const float* __restrict__ Kp,
                            const float* __restrict__ Vp, const int* __restrict__ nbr,
                            const void* __restrict__ validp, const float* __restrict__ rs,
                            float* __restrict__ out, int N) {
    int warp = (blockIdx.x * blockDim.x + threadIdx.x) >> 5;
    int lane = threadIdx.x & 31;
    if (warp >= N) return;
    int i = warp;
    float4 q = ((const float4*)Q)[(size_t)i * 32 + lane];
    bool isbyte = (g_validbyte != 0);
    float d[KNBR];
    float4 v[KNBR];
    #pragma unroll
    for (int j = 0; j < KNBR; j++) {
        int nb = nbr[(size_t)i * KNBR + j];
        int vld = isbyte ? (int)((const unsigned char*)validp)[(size_t)i * KNBR + j]
                         : ((const int*)validp)[(size_t)i * KNBR + j];
        bool masked = (vld == 0) || (rs[nb] == 0.0f);
        float4 k4 = ((const float4*)Kp)[(size_t)nb * 32 + lane];
        v[j]      = ((const float4*)Vp)[(size_t)nb * 32 + lane];
        float p = q.x * k4.x + q.y * k4.y + q.z * k4.z + q.w * k4.w;
        p += __shfl_xor_sync(0xffffffffu, p, 1);
        p += __shfl_xor_sync(0xffffffffu, p, 2);
        d[j] = masked ? -1e30f : p * 0.25f;   // dh^-0.5 = 1/4
    }
    float m = d[0];
    #pragma unroll
    for (int j = 1; j < KNBR; j++) m = fmaxf(m, d[j]);
    float e[KNBR], s = 0.f;
    #pragma unroll
    for (int j = 0; j < KNBR; j++) { e[j] = __expf(d[j] - m); s += e[j]; }
    float inv = 1.f / s;
    float4 o = make_float4(0.f, 0.f, 0.f, 0.f);
    #pragma unroll
    for (int j = 0; j < KNBR; j++) {
        float a = e[j] * inv;
        o.x += a * v[j].x; o.y += a * v[j].y; o.z += a * v[j].z; o.w += a * v[j].w;
    }
    ((float4*)out)[(size_t)i * 32 + lane] = o;
}

// ---------------- host orchestration ----------------------------------------
extern "C" void kernel_launch(void* const* d_in, const int* in_sizes, int n_in,
                              void* d_out, int out_size) {
    const float* feat  = (const float*)d_in[0];
    const int*   nbr   = (const int*)d_in[1];
    const void*  valid = d_in[2];
    const float* wq1 = (const float*)d_in[3];
    const float* wk1 = (const float*)d_in[4];
    const float* wv1 = (const float*)d_in[5];
    const float* wo1 = (const float*)d_in[6];
    const float* bo1 = (const float*)d_in[7];
    const float* w1a = (const float*)d_in[8];
    const float* b1a = (const float*)d_in[9];
    const float* w1b = (const float*)d_in[10];
    const float* b1b = (const float*)d_in[11];
    const float* g1a = (const float*)d_in[12];
    const float* be1a= (const float*)d_in[13];
    const float* g1b = (const float*)d_in[14];
    const float* be1b= (const float*)d_in[15];
    const float* wq2 = (const float*)d_in[16];
    const float* wk2 = (const float*)d_in[17];
    const float* wv2 = (const float*)d_in[18];
    const float* wo2 = (const float*)d_in[19];
    const float* bo2 = (const float*)d_in[20];
    const float* w2a = (const float*)d_in[21];
    const float* b2a = (const float*)d_in[22];
    const float* w2b = (const float*)d_in[23];
    const float* b2b = (const float*)d_in[24];
    const float* g2a = (const float*)d_in[25];
    const float* be2a= (const float*)d_in[26];
    const float* g2b = (const float*)d_in[27];
    const float* be2b= (const float*)d_in[28];
    const float* w4  = (const float*)d_in[29];
    const float* b4  = (const float*)d_in[30];

    int N = in_sizes[0] / D;

    float *Q1, *K1, *V1, *K2, *V2, *Q2, *ATT, *XB, *RS;
    cudaGetSymbolAddress((void**)&Q1,  g_Q1);
    cudaGetSymbolAddress((void**)&K1,  g_K1);
    cudaGetSymbolAddress((void**)&V1,  g_V1);
    cudaGetSymbolAddress((void**)&K2,  g_K2);
    cudaGetSymbolAddress((void**)&V2,  g_V2);
    cudaGetSymbolAddress((void**)&Q2,  g_Q2);
    cudaGetSymbolAddress((void**)&ATT, g_ATT);
    cudaGetSymbolAddress((void**)&XB,  g_XB);
    cudaGetSymbolAddress((void**)&RS,  g_rs);

    int MB  = (N + 127) / 128;
    int WPB = (N + 7) / 8;

    const int PROJ_SMEM  = (8 * 128 * 20 + 2 * 16 * 136) * 4;                   // 99328 B
    const int LAYER_SMEM = (2 * 8 * 128 * 20 + 2 * 16 * 136 + 128 * 4 * 2) * 4; // 185344 B
    cudaFuncSetAttribute(proj5_kernel, cudaFuncAttributeMaxDynamicSharedMemorySize, PROJ_SMEM);
    cudaFuncSetAttribute(layer_kernel<128, 1, 0>, cudaFuncAttributeMaxDynamicSharedMemorySize, LAYER_SMEM);
    cudaFuncSetAttribute(layer_kernel<64, 0, 1>,  cudaFuncAttributeMaxDynamicSharedMemorySize, LAYER_SMEM);

    detect_valid_kernel<<<1, 1024>>>((const unsigned char*)valid, N * KNBR);

    Proj5 p;
    p.W[0] = wq1; p.W[1] = wk1; p.W[2] = wv1; p.W[3] = wk2; p.W[4] = wv2;
    p.Y[0] = Q1;  p.Y[1] = K1;  p.Y[2] = V1;  p.Y[3] = K2;  p.Y[4] = V2;
    proj5_kernel<<<MB, 256, PROJ_SMEM>>>(feat, p, RS, N);

    // ---- layer 1: writes XB (residual for layer 2) and Q2 = XB@wq2 ----
    attn_kernel<<<WPB, 256>>>(Q1, K1, V1, nbr, valid, RS, ATT, N);
    layer_kernel<128, 1, 0><<<MB, 512, LAYER_SMEM>>>(
        ATT, wo1, bo1, feat, g1a, be1a, w1a, b1a, w1b, b1b, g1b, be1b,
        wq2, nullptr, XB, Q2, N);

    // ---- layer 2: post = tanh(XB@w4 + b4) straight to d_out ----
    attn_kernel<<<WPB, 256>>>(Q2, K2, V2, nbr, valid, RS, ATT, N);
    layer_kernel<64, 0, 1><<<MB, 512, LAYER_SMEM>>>(
        ATT, wo2, bo2, XB, g2a, be2a, w2a, b2a, w2b, b2b, g2b, be2b,
        w4, b4, nullptr, (float*)d_out, N);
}

// round 8
// speedup vs baseline: 3.5058x; 1.1371x over previous
#include <cuda_runtime.h>
#include <math.h>

#define D 128
#define KNBR 5
#define NMAX 300000

// ---------------- scratch (static device memory; no allocations allowed) ----
__device__ float g_Q1[(size_t)NMAX * D];
__device__ float g_K1[(size_t)NMAX * D];
__device__ float g_V1[(size_t)NMAX * D];
__device__ float g_K2[(size_t)NMAX * D];
__device__ float g_V2[(size_t)NMAX * D];
__device__ float g_Q2[(size_t)NMAX * D];
__device__ float g_ATT[(size_t)NMAX * D];
__device__ float g_XB[(size_t)NMAX * D];
__device__ float g_rs[NMAX];
__device__ int   g_validbyte;
__device__ float g_Wr[270336];      // tf32-pre-rounded weights

// offsets into g_Wr
#define OFF_WQ1 0
#define OFF_WK1 16384
#define OFF_WV1 32768
#define OFF_WK2 49152
#define OFF_WV2 65536
#define OFF_WO1 81920
#define OFF_W1A 98304
#define OFF_W1B 131072
#define OFF_WQ2 163840
#define OFF_WO2 180224
#define OFF_W2A 196608
#define OFF_W2B 229376
#define OFF_W4  262144

// ---------------- detect whether nbr_valid is byte-bool or int32 ------------
__global__ void detect_valid_kernel(const unsigned char* __restrict__ p, int nelem) {
    if (threadIdx.x == 0) g_validbyte = 0;
    __syncthreads();
    int lim = nelem < 4096 ? nelem : 4096;
    int found = 0;
    for (int j = threadIdx.x; j < lim; j += blockDim.x)
        if ((j & 3) && p[j]) found = 1;
    if (found) g_validbyte = 1;
}

// ---------------- tf32 / mma / cp.async helpers ------------------------------
__device__ __forceinline__ unsigned f2tf32(float f) {
    unsigned u;
    asm("cvt.rna.tf32.f32 %0, %1;" : "=r"(u) : "f"(f));
    return u;
}
__device__ __forceinline__ float rnd_tf32(float f) { return __uint_as_float(f2tf32(f)); }

__device__ __forceinline__ void mma_tf32(float* c, const unsigned* a, const unsigned* b) {
    asm volatile(
        "mma.sync.aligned.m16n8k8.row.col.f32.tf32.tf32.f32 "
        "{%0,%1,%2,%3}, {%4,%5,%6,%7}, {%8,%9}, {%0,%1,%2,%3};"
        : "+f"(c[0]), "+f"(c[1]), "+f"(c[2]), "+f"(c[3])
        : "r"(a[0]), "r"(a[1]), "r"(a[2]), "r"(a[3]), "r"(b[0]), "r"(b[1]));
}

__device__ __forceinline__ void cp16(float* dst, const float* src, bool pred) {
    unsigned sa = (unsigned)__cvta_generic_to_shared(dst);
    int sz = pred ? 16 : 0;
    asm volatile("cp.async.cg.shared.global [%0], [%1], 16, %2;"
                 :: "r"(sa), "l"(src), "r"(sz) : "memory");
}
#define CP_COMMIT asm volatile("cp.async.commit_group;" ::: "memory")
__device__ __forceinline__ void cp_wait1() { asm volatile("cp.async.wait_group 1;" ::: "memory"); }
__device__ __forceinline__ void cp_wait0() { asm volatile("cp.async.wait_group 0;" ::: "memory"); }

// ---------------- weight pre-rounding pass -----------------------------------
struct PrepList { const float* src[13]; int len[13]; int off[13]; };

__global__ void prep_weights(PrepList pl, float* __restrict__ dst) {
    int stride = gridDim.x * blockDim.x;
    int t = blockIdx.x * blockDim.x + threadIdx.x;
    #pragma unroll 1
    for (int e = 0; e < 13; e++) {
        const float* s = pl.src[e];
        float* d = dst + pl.off[e];
        for (int i = t; i < pl.len[e]; i += stride)
            d[i] = rnd_tf32(s[i]);
    }
}

// ============================================================================
//  Fragment compute: A in [128][20] chunk, B in [16][136] stage.
//  Operands are pre-rounded tf32 values -> raw bit-cast, no cvt.
// ============================================================================
template <int NT>
__device__ __forceinline__ void compute_stageN(
    const float* __restrict__ Asm, const float* __restrict__ Bsm,
    int lane, int mrow, int ncol, float (&c)[2][NT][4])
{
    #pragma unroll
    for (int ks = 0; ks < 16; ks += 8) {
        int kq = ks + (lane & 3);
        unsigned a[2][4], b[NT][2];
        #pragma unroll
        for (int mt = 0; mt < 2; mt++) {
            int row = mrow + mt * 16 + (lane >> 2);
            a[mt][0] = __float_as_uint(Asm[row * 20 + kq]);
            a[mt][1] = __float_as_uint(Asm[(row + 8) * 20 + kq]);
            a[mt][2] = __float_as_uint(Asm[row * 20 + kq + 4]);
            a[mt][3] = __float_as_uint(Asm[(row + 8) * 20 + kq + 4]);
        }
        #pragma unroll
        for (int nt = 0; nt < NT; nt++) {
            int col = ncol + nt * 8 + (lane >> 2);
            b[nt][0] = __float_as_uint(Bsm[kq * 136 + col]);
            b[nt][1] = __float_as_uint(Bsm[(kq + 4) * 136 + col]);
        }
        #pragma unroll
        for (int mt = 0; mt < 2; mt++)
            #pragma unroll
            for (int nt = 0; nt < NT; nt++)
                mma_tf32(c[mt][nt], a[mt], b[nt]);
    }
}

// Stream B (K=128, 4 stages of 32) against a resident A region [8][128][20].
// blockDim must be 512.
template <int NT>
__device__ __forceinline__ void gemm_stream(
    const float* __restrict__ Areg, const float* __restrict__ W,
    int pitch, int colOff, float* __restrict__ Bsm,
    int tid, int lane, int mrow, int ncol, float (&c)[2][NT][4])
{
    constexpr int PERROW = NT * 8;               // cp16 per k-row
    constexpr int ITER   = (32 * PERROW) / 512;  // cp16 per thread per stage
    #pragma unroll
    for (int r = 0; r < ITER; r++) {
        int idx = tid + r * 512;
        int bk = idx / PERROW, bc = (idx % PERROW) * 4;
        cp16(&Bsm[bk * 136 + bc], W + (size_t)bk * pitch + colOff + bc, true);
    }
    CP_COMMIT;
    #pragma unroll
    for (int it = 0; it < 4; it++) {
        if (it < 3) {
            int st = (it + 1) & 1, k0 = (it + 1) * 32;
            #pragma unroll
            for (int r = 0; r < ITER; r++) {
                int idx = tid + r * 512;
                int bk = idx / PERROW, bc = (idx % PERROW) * 4;
                cp16(&Bsm[st * (32 * 136) + bk * 136 + bc],
                     W + (size_t)(k0 + bk) * pitch + colOff + bc, true);
            }
            CP_COMMIT;
            cp_wait1();
        } else {
            cp_wait0();
        }
        __syncthreads();
        const float* Bst = Bsm + (it & 1) * (32 * 136);
        compute_stageN<NT>(Areg + (2 * it) * 2560,     Bst,            lane, mrow, ncol, c);
        compute_stageN<NT>(Areg + (2 * it + 1) * 2560, Bst + 16 * 136, lane, mrow, ncol, c);
        __syncthreads();
    }
}

// bias + residual (global or smem A-layout) + LayerNorm; output (tf32-rounded)
// to smem A-layout and/or global. Overwrites c with pre-LN values.
__device__ __forceinline__ void ln_epi(
    float (&c)[2][4][4], const float* __restrict__ bias,
    const float* __restrict__ resg, const float* __restrict__ ressm,
    const float* __restrict__ gam, const float* __restrict__ bet,
    float2* __restrict__ red, float* __restrict__ outsm, float* __restrict__ outg,
    int row0, int M, int lane, int warp, int mrow, int ncol)
{
    int warpN = warp & 3;
    #pragma unroll
    for (int mt = 0; mt < 2; mt++)
        #pragma unroll
        for (int rh = 0; rh < 2; rh++) {
            int rl = mrow + mt * 16 + rh * 8 + (lane >> 2);
            bool ok = row0 + rl < M;
            float s = 0.f, sq = 0.f;
            #pragma unroll
            for (int nt = 0; nt < 4; nt++) {
                int col = ncol + nt * 8 + (lane & 3) * 2;
                float2 rr;
                if (ressm) rr = *(const float2*)&ressm[(col >> 4) * 2560 + rl * 20 + (col & 15)];
                else rr = ok ? *(const float2*)&resg[(size_t)(row0 + rl) * 128 + col]
                             : make_float2(0.f, 0.f);
                float2 bb = *(const float2*)&bias[col];
                float x0 = c[mt][nt][rh * 2 + 0] + rr.x + bb.x;
                float x1 = c[mt][nt][rh * 2 + 1] + rr.y + bb.y;
                c[mt][nt][rh * 2 + 0] = x0;
                c[mt][nt][rh * 2 + 1] = x1;
                s += x0 + x1;
                sq += x0 * x0 + x1 * x1;
            }
            s  += __shfl_xor_sync(0xffffffffu, s, 1);
            s  += __shfl_xor_sync(0xffffffffu, s, 2);
            sq += __shfl_xor_sync(0xffffffffu, sq, 1);
            sq += __shfl_xor_sync(0xffffffffu, sq, 2);
            if ((lane & 3) == 0) red[rl * 4 + warpN] = make_float2(s, sq);
        }
    __syncthreads();
    #pragma unroll
    for (int mt = 0; mt < 2; mt++)
        #pragma unroll
        for (int rh = 0; rh < 2; rh++) {
            int rl = mrow + mt * 16 + rh * 8 + (lane >> 2);
            float s = 0.f, sq = 0.f;
            #pragma unroll
            for (int wN = 0; wN < 4; wN++) { float2 e = red[rl * 4 + wN]; s += e.x; sq += e.y; }
            float mean = s * (1.f / 128.f);
            float var  = sq * (1.f / 128.f) - mean * mean;
            float rstd = rsqrtf(var + 1e-5f);
            bool ok = row0 + rl < M;
            #pragma unroll
            for (int nt = 0; nt < 4; nt++) {
                int col = ncol + nt * 8 + (lane & 3) * 2;
                float2 gg = *(const float2*)&gam[col];
                float2 ee = *(const float2*)&bet[col];
                float2 o;
                o.x = rnd_tf32((c[mt][nt][rh * 2 + 0] - mean) * rstd * gg.x + ee.x);
                o.y = rnd_tf32((c[mt][nt][rh * 2 + 1] - mean) * rstd * gg.y + ee.y);
                if (outsm) *(float2*)&outsm[(col >> 4) * 2560 + rl * 20 + (col & 15)] = o;
                if (outg && ok) *(float2*)&outg[(size_t)(row0 + rl) * 128 + col] = o;
            }
        }
    __syncthreads();
}

// relu(c + bias) -> smem A-layout (tf32-rounded); zeros c for reuse.
__device__ __forceinline__ void store_relu_sm(
    float (&c)[2][4][4], const float* __restrict__ bias, float* __restrict__ outsm,
    int lane, int mrow, int ncol)
{
    #pragma unroll
    for (int mt = 0; mt < 2; mt++)
        #pragma unroll
        for (int rh = 0; rh < 2; rh++) {
            int rl = mrow + mt * 16 + rh * 8 + (lane >> 2);
            #pragma unroll
            for (int nt = 0; nt < 4; nt++) {
                int col = ncol + nt * 8 + (lane & 3) * 2;
                float2 bb = *(const float2*)&bias[col];
                float2 o;
                o.x = rnd_tf32(fmaxf(c[mt][nt][rh * 2 + 0] + bb.x, 0.f));
                o.y = rnd_tf32(fmaxf(c[mt][nt][rh * 2 + 1] + bb.y, 0.f));
                *(float2*)&outsm[(col >> 4) * 2560 + rl * 20 + (col & 15)] = o;
                c[mt][nt][rh * 2 + 0] = 0.f;
                c[mt][nt][rh * 2 + 1] = 0.f;
            }
        }
}

// ============================================================================
//  Mega layer kernel. 512 threads, 1 CTA/SM.
// ============================================================================
template <int NP, int WRITE_XB, int POSTTANH>
__global__ void __launch_bounds__(512, 1) layer_kernel(
    const float* __restrict__ ATT, const float* __restrict__ wo, const float* __restrict__ bo,
    const float* __restrict__ res, const float* __restrict__ ga, const float* __restrict__ bea,
    const float* __restrict__ wa, const float* __restrict__ ba,
    const float* __restrict__ wb, const float* __restrict__ bb,
    const float* __restrict__ gb, const float* __restrict__ beb,
    const float* __restrict__ Wp, const float* __restrict__ bp,
    float* __restrict__ XB, float* __restrict__ Yp, int M)
{
    extern __shared__ float sm[];
    float*  R1  = sm;                        // XA, [8][128][20]
    float*  R2  = R1 + 8 * 128 * 20;         // ATT / H-half / XB tile
    float*  Bsm = R2 + 8 * 128 * 20;         // [2][32][136]
    float2* red = (float2*)(Bsm + 2 * 32 * 136);   // [128][4]

    int row0 = blockIdx.x * 128;
    int tid = threadIdx.x, lane = tid & 31, warp = tid >> 5;
    int mrow = (warp >> 2) * 32;
    int ncol = (warp & 3) * 32;

    // stage ATT tile -> R2 (ATT is pre-rounded tf32 by attn_kernel)
    {
        int row = tid >> 2, seg = (tid & 3) * 4;
        bool ok = row0 + row < M;
        const float* src = ATT + (size_t)(row0 + row) * 128 + seg;
        #pragma unroll
        for (int kc = 0; kc < 8; kc++)
            cp16(&R2[kc * 2560 + row * 20 + seg], ok ? src + kc * 16 : ATT, ok);
        CP_COMMIT;
    }

    float cA[2][4][4] = {};
    float cB[2][4][4] = {};

    // P1: cA = ATT @ wo
    gemm_stream<4>(R2, wo, 128, 0, Bsm, tid, lane, mrow, ncol, cA);
    // P2: XA = LN(cA + bo + res) -> R1 (smem only)
    ln_epi(cA, bo, res, nullptr, ga, bea, red, R1, nullptr, row0, M, lane, warp, mrow, ncol);

    #pragma unroll
    for (int mt = 0; mt < 2; mt++)
        #pragma unroll
        for (int nt = 0; nt < 4; nt++)
            #pragma unroll
            for (int q = 0; q < 4; q++) cA[mt][nt][q] = 0.f;

    // FFN in two 128-col halves, H resident in R2
    #pragma unroll
    for (int h = 0; h < 2; h++) {
        gemm_stream<4>(R1, wa, 256, h * 128, Bsm, tid, lane, mrow, ncol, cA);
        store_relu_sm(cA, ba + h * 128, R2, lane, mrow, ncol);   // also zeros cA
        gemm_stream<4>(R2, wb + (size_t)h * 128 * 128, 128, 0, Bsm, tid, lane, mrow, ncol, cB);
    }

    // XB = LN(cB + bb + XA[smem]) -> R2 (for post) and optionally global
    ln_epi(cB, bb, nullptr, R1, gb, beb, red, R2, WRITE_XB ? XB : nullptr,
           row0, M, lane, warp, mrow, ncol);

    // post: Yp = act(XB @ Wp + bp)
    constexpr int NTP = NP / 32;
    int ncolp = (warp & 3) * (NTP * 8);
    float cP[2][NTP][4] = {};
    gemm_stream<NTP>(R2, Wp, NP, 0, Bsm, tid, lane, mrow, ncolp, cP);

    const bool hasb = (bp != nullptr);
    #pragma unroll
    for (int mt = 0; mt < 2; mt++)
        #pragma unroll
        for (int rh = 0; rh < 2; rh++) {
            int rl = mrow + mt * 16 + rh * 8 + (lane >> 2);
            if (row0 + rl >= M) continue;
            #pragma unroll
            for (int nt = 0; nt < NTP; nt++) {
                int col = ncolp + nt * 8 + (lane & 3) * 2;
                float bx = 0.f, by = 0.f;
                if (hasb) { float2 v = *(const float2*)&bp[col]; bx = v.x; by = v.y; }
                float x0 = cP[mt][nt][rh * 2 + 0] + bx;
                float x1 = cP[mt][nt][rh * 2 + 1] + by;
                if (POSTTANH) { x0 = tanhf(x0); x1 = tanhf(x1); }
                *(float2*)&Yp[(size_t)(row0 + rl) * NP + col] = make_float2(x0, x1);
            }
        }
}

// ---------------- proj5: fused 5-way projection, A resident ------------------
struct Proj5 { const float* W[5]; float* Y[5]; };

__device__ __forceinline__ void compute_stage8(
    const float* __restrict__ Asm, const float* __restrict__ Bsm,
    int lane, int mrow, int ncol, float (&c)[2][8][4])
{
    #pragma unroll
    for (int ks = 0; ks < 16; ks += 8) {
        int kq = ks + (lane & 3);
        unsigned a[2][4], b[8][2];
        #pragma unroll
        for (int mt = 0; mt < 2; mt++) {
            int row = mrow + mt * 16 + (lane >> 2);
            a[mt][0] = __float_as_uint(Asm[row * 20 + kq]);
            a[mt][1] = __float_as_uint(Asm[(row + 8) * 20 + kq]);
            a[mt][2] = __float_as_uint(Asm[row * 20 + kq + 4]);
            a[mt][3] = __float_as_uint(Asm[(row + 8) * 20 + kq + 4]);
        }
        #pragma unroll
        for (int nt = 0; nt < 8; nt++) {
            int col = ncol + nt * 8 + (lane >> 2);
            b[nt][0] = __float_as_uint(Bsm[kq * 136 + col]);
            b[nt][1] = __float_as_uint(Bsm[(kq + 4) * 136 + col]);
        }
        #pragma unroll
        for (int mt = 0; mt < 2; mt++)
            #pragma unroll
            for (int nt = 0; nt < 8; nt++)
                mma_tf32(c[mt][nt], a[mt], b[nt]);
    }
}

__global__ void __launch_bounds__(256, 1) proj5_kernel(
    const float* __restrict__ X, Proj5 p, float* __restrict__ rs, int M)
{
    extern __shared__ float sm[];
    float (*Af)[128][20] = (float(*)[128][20])sm;
    float (*Bs)[16][136] = (float(*)[16][136])(sm + 8 * 128 * 20);
    int row0 = blockIdx.x * 128;
    int tid = threadIdx.x, lane = tid & 31, warp = tid >> 5;
    int mrow = (warp >> 1) * 32, ncol = (warp & 1) * 64;

    {
        int row = tid >> 1;
        int seg = (tid & 1) * 2;
        bool ok = (row0 + row) < M;
        #pragma unroll
        for (int kc = 0; kc < 8; kc++) {
            const float* sa = X + (size_t)(row0 + row) * 128 + kc * 16 + seg * 4;
            cp16(&Af[kc][row][seg * 4],     ok ? sa     : X, ok);
            cp16(&Af[kc][row][seg * 4 + 4], ok ? sa + 4 : X, ok);
        }
        CP_COMMIT;
    }
    int s_bk = tid >> 4;
    int s_bc = (tid & 15) * 8;
    {
        const float* sb = p.W[0] + (size_t)s_bk * 128 + s_bc;
        cp16(&Bs[0][s_bk][s_bc],     sb,     true);
        cp16(&Bs[0][s_bk][s_bc + 4], sb + 4, true);
        CP_COMMIT;
    }

    float c[2][8][4] = {};
    for (int it = 0; it < 40; it++) {
        int kc = it & 7;
        if (it + 1 < 40) {
            int st = (it + 1) & 1;
            const float* Wn = p.W[(it + 1) >> 3];
            int k0 = ((it + 1) & 7) * 16;
            const float* sb = Wn + (size_t)(k0 + s_bk) * 128 + s_bc;
            cp16(&Bs[st][s_bk][s_bc],     sb,     true);
            cp16(&Bs[st][s_bk][s_bc + 4], sb + 4, true);
            CP_COMMIT;
            cp_wait1();
        } else {
            cp_wait0();
        }
        __syncthreads();
        if (it == 0) {
            int row = tid >> 1, half = tid & 1;
            float s = 0.f;
            #pragma unroll
            for (int q = 0; q < 4; q++) {
                int kcc = half * 4 + q;
                #pragma unroll
                for (int kl = 0; kl < 16; kl++) s += Af[kcc][row][kl];
            }
            s += __shfl_xor_sync(0xffffffffu, s, 1);
            if (half == 0 && row0 + row < M) rs[row0 + row] = s;
        }
        compute_stage8(&Af[kc][0][0], &Bs[it & 1][0][0], lane, mrow, ncol, c);
        __syncthreads();
        if (kc == 7) {
            float* Y = p.Y[it >> 3];
            #pragma unroll
            for (int mt = 0; mt < 2; mt++)
                #pragma unroll
                for (int nt = 0; nt < 8; nt++) {
                    int col = ncol + nt * 8 + (lane & 3) * 2;
                    #pragma unroll
                    for (int rh = 0; rh < 2; rh++) {
                        int row = row0 + mrow + mt * 16 + rh * 8 + (lane >> 2);
                        if (row < M)
                            *(float2*)&Y[(size_t)row * 128 + col] =
                                make_float2(c[mt][nt][rh * 2 + 0], c[mt][nt][rh * 2 + 1]);
                        c[mt][nt][rh * 2 + 0] = 0.f;
                        c[mt][nt][rh * 2 + 1] = 0.f;
                    }
                }
        }
    }
}

// ---------------- warp-per-node attention (output tf32-rounded) --------------
__global__ void attn_kernel(const float* __restrict__ Q, const float* __restrict__ Kp,
                            const float* __restrict__ Vp, const int* __restrict__ nbr,
                            const void* __restrict__ validp, const float* __restrict__ rs,
                            float* __restrict__ out, int N) {
    int warp = (blockIdx.x * blockDim.x + threadIdx.x) >> 5;
    int lane = threadIdx.x & 31;
    if (warp >= N) return;
    int i = warp;
    float4 q = ((const float4*)Q)[(size_t)i * 32 + lane];
    bool isbyte = (g_validbyte != 0);
    float d[KNBR];
    float4 v[KNBR];
    #pragma unroll
    for (int j = 0; j < KNBR; j++) {
        int nb = nbr[(size_t)i * KNBR + j];
        int vld = isbyte ? (int)((const unsigned char*)validp)[(size_t)i * KNBR + j]
                         : ((const int*)validp)[(size_t)i * KNBR + j];
        bool masked = (vld == 0) || (rs[nb] == 0.0f);
        float4 k4 = ((const float4*)Kp)[(size_t)nb * 32 + lane];
        v[j]      = ((const float4*)Vp)[(size_t)nb * 32 + lane];
        float p = q.x * k4.x + q.y * k4.y + q.z * k4.z + q.w * k4.w;
        p += __shfl_xor_sync(0xffffffffu, p, 1);
        p += __shfl_xor_sync(0xffffffffu, p, 2);
        d[j] = masked ? -1e30f : p * 0.25f;   // dh^-0.5 = 1/4
    }
    float m = d[0];
    #pragma unroll
    for (int j = 1; j < KNBR; j++) m = fmaxf(m, d[j]);
    float e[KNBR], s = 0.f;
    #pragma unroll
    for (int j = 0; j < KNBR; j++) { e[j] = __expf(d[j] - m); s += e[j]; }
    float inv = 1.f / s;
    float4 o = make_float4(0.f, 0.f, 0.f, 0.f);
    #pragma unroll
    for (int j = 0; j < KNBR; j++) {
        float a = e[j] * inv;
        o.x += a * v[j].x; o.y += a * v[j].y; o.z += a * v[j].z; o.w += a * v[j].w;
    }
    o.x = rnd_tf32(o.x); o.y = rnd_tf32(o.y);
    o.z = rnd_tf32(o.z); o.w = rnd_tf32(o.w);
    ((float4*)out)[(size_t)i * 32 + lane] = o;
}

// ---------------- host orchestration ----------------------------------------
extern "C" void kernel_launch(void* const* d_in, const int* in_sizes, int n_in,
                              void* d_out, int out_size) {
    const float* feat  = (const float*)d_in[0];
    const int*   nbr   = (const int*)d_in[1];
    const void*  valid = d_in[2];
    const float* wq1 = (const float*)d_in[3];
    const float* wk1 = (const float*)d_in[4];
    const float* wv1 = (const float*)d_in[5];
    const float* wo1 = (const float*)d_in[6];
    const float* bo1 = (const float*)d_in[7];
    const float* w1a = (const float*)d_in[8];
    const float* b1a = (const float*)d_in[9];
    const float* w1b = (const float*)d_in[10];
    const float* b1b = (const float*)d_in[11];
    const float* g1a = (const float*)d_in[12];
    const float* be1a= (const float*)d_in[13];
    const float* g1b = (const float*)d_in[14];
    const float* be1b= (const float*)d_in[15];
    const float* wq2 = (const float*)d_in[16];
    const float* wk2 = (const float*)d_in[17];
    const float* wv2 = (const float*)d_in[18];
    const float* wo2 = (const float*)d_in[19];
    const float* bo2 = (const float*)d_in[20];
    const float* w2a = (const float*)d_in[21];
    const float* b2a = (const float*)d_in[22];
    const float* w2b = (const float*)d_in[23];
    const float* b2b = (const float*)d_in[24];
    const float* g2a = (const float*)d_in[25];
    const float* be2a= (const float*)d_in[26];
    const float* g2b = (const float*)d_in[27];
    const float* be2b= (const float*)d_in[28];
    const float* w4  = (const float*)d_in[29];
    const float* b4  = (const float*)d_in[30];

    int N = in_sizes[0] / D;

    float *Q1, *K1, *V1, *K2, *V2, *Q2, *ATT, *XB, *RS, *WR;
    cudaGetSymbolAddress((void**)&Q1,  g_Q1);
    cudaGetSymbolAddress((void**)&K1,  g_K1);
    cudaGetSymbolAddress((void**)&V1,  g_V1);
    cudaGetSymbolAddress((void**)&K2,  g_K2);
    cudaGetSymbolAddress((void**)&V2,  g_V2);
    cudaGetSymbolAddress((void**)&Q2,  g_Q2);
    cudaGetSymbolAddress((void**)&ATT, g_ATT);
    cudaGetSymbolAddress((void**)&XB,  g_XB);
    cudaGetSymbolAddress((void**)&RS,  g_rs);
    cudaGetSymbolAddress((void**)&WR,  g_Wr);

    int MB  = (N + 127) / 128;
    int WPB = (N + 7) / 8;

    const int PROJ_SMEM  = (8 * 128 * 20 + 2 * 16 * 136) * 4;                   // 99328 B
    const int LAYER_SMEM = (2 * 8 * 128 * 20 + 2 * 32 * 136 + 128 * 4 * 2) * 4; // 202752 B
    cudaFuncSetAttribute(proj5_kernel, cudaFuncAttributeMaxDynamicSharedMemorySize, PROJ_SMEM);
    cudaFuncSetAttribute(layer_kernel<128, 1, 0>, cudaFuncAttributeMaxDynamicSharedMemorySize, LAYER_SMEM);
    cudaFuncSetAttribute(layer_kernel<64, 0, 1>,  cudaFuncAttributeMaxDynamicSharedMemorySize, LAYER_SMEM);

    detect_valid_kernel<<<1, 1024>>>((const unsigned char*)valid, N * KNBR);

    // pre-round all mma weight operands to tf32
    PrepList pl;
    const float* srcs[13] = {wq1, wk1, wv1, wk2, wv2, wo1, w1a, w1b, wq2, wo2, w2a, w2b, w4};
    int lens[13] = {16384,16384,16384,16384,16384, 16384, 32768, 32768, 16384, 16384, 32768, 32768, 8192};
    int offs[13] = {OFF_WQ1,OFF_WK1,OFF_WV1,OFF_WK2,OFF_WV2, OFF_WO1, OFF_W1A, OFF_W1B,
                    OFF_WQ2, OFF_WO2, OFF_W2A, OFF_W2B, OFF_W4};
    for (int e = 0; e < 13; e++) { pl.src[e] = srcs[e]; pl.len[e] = lens[e]; pl.off[e] = offs[e]; }
    prep_weights<<<120, 256>>>(pl, WR);

    Proj5 p;
    p.W[0] = WR + OFF_WQ1; p.W[1] = WR + OFF_WK1; p.W[2] = WR + OFF_WV1;
    p.W[3] = WR + OFF_WK2; p.W[4] = WR + OFF_WV2;
    p.Y[0] = Q1;  p.Y[1] = K1;  p.Y[2] = V1;  p.Y[3] = K2;  p.Y[4] = V2;
    proj5_kernel<<<MB, 256, PROJ_SMEM>>>(feat, p, RS, N);

    // ---- layer 1: writes XB (residual for layer 2) and Q2 = XB@wq2 ----
    attn_kernel<<<WPB, 256>>>(Q1, K1, V1, nbr, valid, RS, ATT, N);
    layer_kernel<128, 1, 0><<<MB, 512, LAYER_SMEM>>>(
        ATT, WR + OFF_WO1, bo1, feat, g1a, be1a, WR + OFF_W1A, b1a, WR + OFF_W1B, b1b, g1b, be1b,
        WR + OFF_WQ2, nullptr, XB, Q2, N);

    // ---- layer 2: post = tanh(XB@w4 + b4) straight to d_out ----
    attn_kernel<<<WPB, 256>>>(Q2, K2, V2, nbr, valid, RS, ATT, N);
    layer_kernel<64, 0, 1><<<MB, 512, LAYER_SMEM>>>(
        ATT, WR + OFF_WO2, bo2, XB, g2a, be2a, WR + OFF_W2A, b2a, WR + OFF_W2B, b2b, g2b, be2b,
        WR + OFF_W4, b4, nullptr, (float*)d_out, N);
}

// round 10
// speedup vs baseline: 3.6305x; 1.0356x over previous
#include <cuda_runtime.h>
#include <math.h>

#define D 128
#define KNBR 5
#define NMAX 300000

// ---------------- scratch (static device memory; no allocations allowed) ----
__device__ float g_Q1[(size_t)NMAX * D];
__device__ float g_K1[(size_t)NMAX * D];
__device__ float g_V1[(size_t)NMAX * D];
__device__ float g_K2[(size_t)NMAX * D];
__device__ float g_V2[(size_t)NMAX * D];
__device__ float g_Q2[(size_t)NMAX * D];
__device__ float g_ATT[(size_t)NMAX * D];
__device__ float g_XB[(size_t)NMAX * D];
__device__ float g_rs[NMAX];
__device__ int   g_validbyte;
__device__ float g_Wr[270336];      // tf32-pre-rounded weights

#define OFF_WQ1 0
#define OFF_WK1 16384
#define OFF_WV1 32768
#define OFF_WK2 49152
#define OFF_WV2 65536
#define OFF_WO1 81920
#define OFF_W1A 98304
#define OFF_W1B 131072
#define OFF_WQ2 163840
#define OFF_WO2 180224
#define OFF_W2A 196608
#define OFF_W2B 229376
#define OFF_W4  262144

// ---------------- detect whether nbr_valid is byte-bool or int32 ------------
__global__ void detect_valid_kernel(const unsigned char* __restrict__ p, int nelem) {
    if (threadIdx.x == 0) g_validbyte = 0;
    __syncthreads();
    int lim = nelem < 4096 ? nelem : 4096;
    int found = 0;
    for (int j = threadIdx.x; j < lim; j += blockDim.x)
        if ((j & 3) && p[j]) found = 1;
    if (found) g_validbyte = 1;
}

// ---------------- tf32 / mma / cp.async helpers ------------------------------
__device__ __forceinline__ unsigned f2tf32(float f) {
    unsigned u;
    asm("cvt.rna.tf32.f32 %0, %1;" : "=r"(u) : "f"(f));
    return u;
}
__device__ __forceinline__ float rnd_tf32(float f) { return __uint_as_float(f2tf32(f)); }

__device__ __forceinline__ void mma_tf32(float* c, const unsigned* a, const unsigned* b) {
    asm volatile(
        "mma.sync.aligned.m16n8k8.row.col.f32.tf32.tf32.f32 "
        "{%0,%1,%2,%3}, {%4,%5,%6,%7}, {%8,%9}, {%0,%1,%2,%3};"
        : "+f"(c[0]), "+f"(c[1]), "+f"(c[2]), "+f"(c[3])
        : "r"(a[0]), "r"(a[1]), "r"(a[2]), "r"(a[3]), "r"(b[0]), "r"(b[1]));
}

__device__ __forceinline__ void cp16(float* dst, const float* src, bool pred) {
    unsigned sa = (unsigned)__cvta_generic_to_shared(dst);
    int sz = pred ? 16 : 0;
    asm volatile("cp.async.cg.shared.global [%0], [%1], 16, %2;"
                 :: "r"(sa), "l"(src), "r"(sz) : "memory");
}
#define CP_COMMIT asm volatile("cp.async.commit_group;" ::: "memory")
__device__ __forceinline__ void cp_wait1() { asm volatile("cp.async.wait_group 1;" ::: "memory"); }
__device__ __forceinline__ void cp_wait0() { asm volatile("cp.async.wait_group 0;" ::: "memory"); }

// ---------------- weight pre-rounding pass -----------------------------------
struct PrepList { const float* src[13]; int len[13]; int off[13]; };

__global__ void prep_weights(PrepList pl, float* __restrict__ dst) {
    int stride = gridDim.x * blockDim.x;
    int t = blockIdx.x * blockDim.x + threadIdx.x;
    #pragma unroll 1
    for (int e = 0; e < 13; e++) {
        const float* s = pl.src[e];
        float* d = dst + pl.off[e];
        for (int i = t; i < pl.len[e]; i += stride)
            d[i] = rnd_tf32(s[i]);
    }
}

// ============================================================================
//  Fragment compute: A chunk [64][20], B stage [16][136]; pre-rounded operands.
// ============================================================================
template <int NT>
__device__ __forceinline__ void compute_stageN(
    const float* __restrict__ Asm, const float* __restrict__ Bsm,
    int lane, int mrow, int ncol, float (&c)[2][NT][4])
{
    #pragma unroll
    for (int ks = 0; ks < 16; ks += 8) {
        int kq = ks + (lane & 3);
        unsigned a[2][4], b[NT][2];
        #pragma unroll
        for (int mt = 0; mt < 2; mt++) {
            int row = mrow + mt * 16 + (lane >> 2);
            a[mt][0] = __float_as_uint(Asm[row * 20 + kq]);
            a[mt][1] = __float_as_uint(Asm[(row + 8) * 20 + kq]);
            a[mt][2] = __float_as_uint(Asm[row * 20 + kq + 4]);
            a[mt][3] = __float_as_uint(Asm[(row + 8) * 20 + kq + 4]);
        }
        #pragma unroll
        for (int nt = 0; nt < NT; nt++) {
            int col = ncol + nt * 8 + (lane >> 2);
            b[nt][0] = __float_as_uint(Bsm[kq * 136 + col]);
            b[nt][1] = __float_as_uint(Bsm[(kq + 4) * 136 + col]);
        }
        #pragma unroll
        for (int mt = 0; mt < 2; mt++)
            #pragma unroll
            for (int nt = 0; nt < NT; nt++)
                mma_tf32(c[mt][nt], a[mt], b[nt]);
    }
}

// Stream B (K=128, 8 stages of 16) against a resident A region [8][64][20].
// blockDim = 256.
template <int NT>
__device__ __forceinline__ void gemm_stream(
    const float* __restrict__ Areg, const float* __restrict__ W,
    int pitch, int colOff, float* __restrict__ Bsm,
    int tid, int lane, int mrow, int ncol, float (&c)[2][NT][4])
{
    constexpr int PERROW = NT * 8;            // cp16 per B k-row
    constexpr int ITER   = (16 * PERROW) / 256;
    #pragma unroll
    for (int r = 0; r < ITER; r++) {
        int idx = tid + r * 256;
        int bk = idx / PERROW, bc = (idx % PERROW) * 4;
        cp16(&Bsm[bk * 136 + bc], W + (size_t)bk * pitch + colOff + bc, true);
    }
    CP_COMMIT;
    #pragma unroll
    for (int it = 0; it < 8; it++) {
        if (it < 7) {
            int st = (it + 1) & 1, k0 = (it + 1) * 16;
            #pragma unroll
            for (int r = 0; r < ITER; r++) {
                int idx = tid + r * 256;
                int bk = idx / PERROW, bc = (idx % PERROW) * 4;
                cp16(&Bsm[st * 2176 + bk * 136 + bc],
                     W + (size_t)(k0 + bk) * pitch + colOff + bc, true);
            }
            CP_COMMIT;
            cp_wait1();
        } else {
            cp_wait0();
        }
        __syncthreads();
        compute_stageN<NT>(Areg + it * 1280, Bsm + (it & 1) * 2176, lane, mrow, ncol, c);
        __syncthreads();
    }
}

// bias + residual (global or smem A-layout) + LayerNorm; output (tf32-rounded)
// to smem A-layout and/or global. Overwrites c with pre-LN values.
__device__ __forceinline__ void ln_epi(
    float (&c)[2][4][4], const float* __restrict__ bias,
    const float* __restrict__ resg, const float* __restrict__ ressm,
    const float* __restrict__ gam, const float* __restrict__ bet,
    float2* __restrict__ red, float* __restrict__ outsm, float* __restrict__ outg,
    int row0, int M, int lane, int warp, int mrow, int ncol)
{
    int warpN = warp & 3;
    #pragma unroll
    for (int mt = 0; mt < 2; mt++)
        #pragma unroll
        for (int rh = 0; rh < 2; rh++) {
            int rl = mrow + mt * 16 + rh * 8 + (lane >> 2);
            bool ok = row0 + rl < M;
            float s = 0.f, sq = 0.f;
            #pragma unroll
            for (int nt = 0; nt < 4; nt++) {
                int col = ncol + nt * 8 + (lane & 3) * 2;
                float2 rr;
                if (ressm) rr = *(const float2*)&ressm[(col >> 4) * 1280 + rl * 20 + (col & 15)];
                else rr = ok ? *(const float2*)&resg[(size_t)(row0 + rl) * 128 + col]
                             : make_float2(0.f, 0.f);
                float2 bb = *(const float2*)&bias[col];
                float x0 = c[mt][nt][rh * 2 + 0] + rr.x + bb.x;
                float x1 = c[mt][nt][rh * 2 + 1] + rr.y + bb.y;
                c[mt][nt][rh * 2 + 0] = x0;
                c[mt][nt][rh * 2 + 1] = x1;
                s += x0 + x1;
                sq += x0 * x0 + x1 * x1;
            }
            s  += __shfl_xor_sync(0xffffffffu, s, 1);
            s  += __shfl_xor_sync(0xffffffffu, s, 2);
            sq += __shfl_xor_sync(0xffffffffu, sq, 1);
            sq += __shfl_xor_sync(0xffffffffu, sq, 2);
            if ((lane & 3) == 0) red[rl * 4 + warpN] = make_float2(s, sq);
        }
    __syncthreads();
    #pragma unroll
    for (int mt = 0; mt < 2; mt++)
        #pragma unroll
        for (int rh = 0; rh < 2; rh++) {
            int rl = mrow + mt * 16 + rh * 8 + (lane >> 2);
            float s = 0.f, sq = 0.f;
            #pragma unroll
            for (int wN = 0; wN < 4; wN++) { float2 e = red[rl * 4 + wN]; s += e.x; sq += e.y; }
            float mean = s * (1.f / 128.f);
            float var  = sq * (1.f / 128.f) - mean * mean;
            float rstd = rsqrtf(var + 1e-5f);
            bool ok = row0 + rl < M;
            #pragma unroll
            for (int nt = 0; nt < 4; nt++) {
                int col = ncol + nt * 8 + (lane & 3) * 2;
                float2 gg = *(const float2*)&gam[col];
                float2 ee = *(const float2*)&bet[col];
                float2 o;
                o.x = rnd_tf32((c[mt][nt][rh * 2 + 0] - mean) * rstd * gg.x + ee.x);
                o.y = rnd_tf32((c[mt][nt][rh * 2 + 1] - mean) * rstd * gg.y + ee.y);
                if (outsm) *(float2*)&outsm[(col >> 4) * 1280 + rl * 20 + (col & 15)] = o;
                if (outg && ok) *(float2*)&outg[(size_t)(row0 + rl) * 128 + col] = o;
            }
        }
    __syncthreads();
}

// relu(c + bias) -> smem A-layout (tf32-rounded); zeros c for reuse.
__device__ __forceinline__ void store_relu_sm(
    float (&c)[2][4][4], const float* __restrict__ bias, float* __restrict__ outsm,
    int lane, int mrow, int ncol)
{
    #pragma unroll
    for (int mt = 0; mt < 2; mt++)
        #pragma unroll
        for (int rh = 0; rh < 2; rh++) {
            int rl = mrow + mt * 16 + rh * 8 + (lane >> 2);
            #pragma unroll
            for (int nt = 0; nt < 4; nt++) {
                int col = ncol + nt * 8 + (lane & 3) * 2;
                float2 bb = *(const float2*)&bias[col];
                float2 o;
                o.x = rnd_tf32(fmaxf(c[mt][nt][rh * 2 + 0] + bb.x, 0.f));
                o.y = rnd_tf32(fmaxf(c[mt][nt][rh * 2 + 1] + bb.y, 0.f));
                *(float2*)&outsm[(col >> 4) * 1280 + rl * 20 + (col & 15)] = o;
                c[mt][nt][rh * 2 + 0] = 0.f;
                c[mt][nt][rh * 2 + 1] = 0.f;
            }
        }
}

// ============================================================================
//  Mega layer kernel: 64-row tile, 256 threads, 2 CTAs/SM.
// ============================================================================
template <int NP, int WRITE_XB, int POSTTANH>
__global__ void __launch_bounds__(256, 2) layer_kernel(
    const float* __restrict__ ATT, const float* __restrict__ wo, const float* __restrict__ bo,
    const float* __restrict__ res, const float* __restrict__ ga, const float* __restrict__ bea,
    const float* __restrict__ wa, const float* __restrict__ ba,
    const float* __restrict__ wb, const float* __restrict__ bb,
    const float* __restrict__ gb, const float* __restrict__ beb,
    const float* __restrict__ Wp, const float* __restrict__ bp,
    float* __restrict__ XB, float* __restrict__ Yp, int M)
{
    extern __shared__ float sm[];
    float*  R1  = sm;                        // XA, [8][64][20]
    float*  R2  = R1 + 8 * 64 * 20;          // ATT / H-half / XB tile
    float*  Bsm = R2 + 8 * 64 * 20;          // [2][16][136]
    float2* red = (float2*)(Bsm + 2 * 16 * 136);   // [64][4]

    int row0 = blockIdx.x * 64;
    int tid = threadIdx.x, lane = tid & 31, warp = tid >> 5;
    int mrow = (warp >> 2) * 32;
    int ncol = (warp & 3) * 32;

    // stage ATT tile -> R2 (ATT is pre-rounded tf32 by attn_kernel)
    {
        int row = tid >> 2, seg = (tid & 3) * 4;
        bool ok = row0 + row < M;
        const float* src = ATT + (size_t)(row0 + row) * 128 + seg;
        #pragma unroll
        for (int kc = 0; kc < 8; kc++)
            cp16(&R2[kc * 1280 + row * 20 + seg], ok ? src + kc * 16 : ATT, ok);
        CP_COMMIT;
    }

    float cA[2][4][4] = {};
    float cB[2][4][4] = {};

    // P1: cA = ATT @ wo
    gemm_stream<4>(R2, wo, 128, 0, Bsm, tid, lane, mrow, ncol, cA);
    // P2: XA = LN(cA + bo + res) -> R1 (smem only)
    ln_epi(cA, bo, res, nullptr, ga, bea, red, R1, nullptr, row0, M, lane, warp, mrow, ncol);

    #pragma unroll
    for (int mt = 0; mt < 2; mt++)
        #pragma unroll
        for (int nt = 0; nt < 4; nt++)
            #pragma unroll
            for (int q = 0; q < 4; q++) cA[mt][nt][q] = 0.f;

    // FFN in two 128-col halves, H resident in R2
    #pragma unroll
    for (int h = 0; h < 2; h++) {
        gemm_stream<4>(R1, wa, 256, h * 128, Bsm, tid, lane, mrow, ncol, cA);
        store_relu_sm(cA, ba + h * 128, R2, lane, mrow, ncol);   // also zeros cA
        gemm_stream<4>(R2, wb + (size_t)h * 128 * 128, 128, 0, Bsm, tid, lane, mrow, ncol, cB);
    }

    // XB = LN(cB + bb + XA[smem]) -> R2 (for post) and optionally global
    ln_epi(cB, bb, nullptr, R1, gb, beb, red, R2, WRITE_XB ? XB : nullptr,
           row0, M, lane, warp, mrow, ncol);

    // post: Yp = act(XB @ Wp + bp)
    constexpr int NTP = NP / 32;
    int ncolp = (warp & 3) * (NTP * 8);
    float cP[2][NTP][4] = {};
    gemm_stream<NTP>(R2, Wp, NP, 0, Bsm, tid, lane, mrow, ncolp, cP);

    const bool hasb = (bp != nullptr);
    #pragma unroll
    for (int mt = 0; mt < 2; mt++)
        #pragma unroll
        for (int rh = 0; rh < 2; rh++) {
            int rl = mrow + mt * 16 + rh * 8 + (lane >> 2);
            if (row0 + rl >= M) continue;
            #pragma unroll
            for (int nt = 0; nt < NTP; nt++) {
                int col = ncolp + nt * 8 + (lane & 3) * 2;
                float bx = 0.f, by = 0.f;
                if (hasb) { float2 v = *(const float2*)&bp[col]; bx = v.x; by = v.y; }
                float x0 = cP[mt][nt][rh * 2 + 0] + bx;
                float x1 = cP[mt][nt][rh * 2 + 1] + by;
                if (POSTTANH) { x0 = tanhf(x0); x1 = tanhf(x1); }
                *(float2*)&Yp[(size_t)(row0 + rl) * NP + col] = make_float2(x0, x1);
            }
        }
}

// ---------------- proj5: fused 5-way projection, 64-row tile, 2 CTAs/SM ------
struct Proj5 { const float* W[5]; float* Y[5]; };

__global__ void __launch_bounds__(256, 2) proj5_kernel(
    const float* __restrict__ X, Proj5 p, float* __restrict__ rs, int M)
{
    extern __shared__ float sm[];
    float* Af = sm;                          // [8][64][20]
    float* Bs = sm + 8 * 64 * 20;            // [2][16][136]
    int row0 = blockIdx.x * 64;
    int tid = threadIdx.x, lane = tid & 31, warp = tid >> 5;
    int mrow = (warp >> 2) * 32, ncol = (warp & 3) * 32;

    // load full A tile (8 k-chunks), 4 threads per row
    {
        int row = tid >> 2, seg = (tid & 3) * 4;
        bool ok = (row0 + row) < M;
        const float* sa = X + (size_t)(row0 + row) * 128 + seg;
        #pragma unroll
        for (int kc = 0; kc < 8; kc++)
            cp16(&Af[kc * 1280 + row * 20 + seg], ok ? sa + kc * 16 : X, ok);
        CP_COMMIT;
    }
    int s_bk = tid >> 4;
    int s_bc = (tid & 15) * 8;
    {
        const float* sb = p.W[0] + (size_t)s_bk * 128 + s_bc;
        cp16(&Bs[s_bk * 136 + s_bc],     sb,     true);
        cp16(&Bs[s_bk * 136 + s_bc + 4], sb + 4, true);
        CP_COMMIT;
    }

    float c[2][4][4] = {};
    for (int it = 0; it < 40; it++) {
        int kc = it & 7;
        if (it + 1 < 40) {
            int st = (it + 1) & 1;
            const float* Wn = p.W[(it + 1) >> 3];
            int k0 = ((it + 1) & 7) * 16;
            const float* sb = Wn + (size_t)(k0 + s_bk) * 128 + s_bc;
            cp16(&Bs[st * 2176 + s_bk * 136 + s_bc],     sb,     true);
            cp16(&Bs[st * 2176 + s_bk * 136 + s_bc + 4], sb + 4, true);
            CP_COMMIT;
            cp_wait1();
        } else {
            cp_wait0();
        }
        __syncthreads();
        if (it == 0) {
            // rowsum for the mask, from the resident A tile (4 threads/row)
            int row = tid >> 2, part = tid & 3;
            float s = 0.f;
            #pragma unroll
            for (int q = 0; q < 2; q++) {
                int kcc = part * 2 + q;
                #pragma unroll
                for (int kl = 0; kl < 16; kl++) s += Af[kcc * 1280 + row * 20 + kl];
            }
            s += __shfl_xor_sync(0xffffffffu, s, 1);
            s += __shfl_xor_sync(0xffffffffu, s, 2);
            if ((lane & 3) == 0 && row0 + row < M) rs[row0 + row] = s;
        }
        compute_stageN<4>(Af + kc * 1280, Bs + (it & 1) * 2176, lane, mrow, ncol, c);
        __syncthreads();
        if (kc == 7) {
            float* Y = p.Y[it >> 3];
            #pragma unroll
            for (int mt = 0; mt < 2; mt++)
                #pragma unroll
                for (int nt = 0; nt < 4; nt++) {
                    int col = ncol + nt * 8 + (lane & 3) * 2;
                    #pragma unroll
                    for (int rh = 0; rh < 2; rh++) {
                        int row = row0 + mrow + mt * 16 + rh * 8 + (lane >> 2);
                        if (row < M)
                            *(float2*)&Y[(size_t)row * 128 + col] =
                                make_float2(c[mt][nt][rh * 2 + 0], c[mt][nt][rh * 2 + 1]);
                        c[mt][nt][rh * 2 + 0] = 0.f;
                        c[mt][nt][rh * 2 + 1] = 0.f;
                    }
                }
        }
    }
}

// ---------------- warp-per-node attention (output tf32-rounded) --------------
__global__ void attn_kernel(const float* __restrict__ Q, const float* __restrict__ Kp,
                            const float* __restrict__ Vp, const int* __restrict__ nbr,
                            const void* __restrict__ validp, const float* __restrict__ rs,
                            float* __restrict__ out, int N) {
    int warp = (blockIdx.x * blockDim.x + threadIdx.x) >> 5;
    int lane = threadIdx.x & 31;
    if (warp >= N) return;
    int i = warp;
    float4 q = ((const float4*)Q)[(size_t)i * 32 + lane];
    bool isbyte = (g_validbyte != 0);
    float d[KNBR];
    float4 v[KNBR];
    #pragma unroll
    for (int j = 0; j < KNBR; j++) {
        int nb = nbr[(size_t)i * KNBR + j];
        int vld = isbyte ? (int)((const unsigned char*)validp)[(size_t)i * KNBR + j]
                         : ((const int*)validp)[(size_t)i * KNBR + j];
        bool masked = (vld == 0) || (rs[nb] == 0.0f);
        float4 k4 = ((const float4*)Kp)[(size_t)nb * 32 + lane];
        v[j]      = ((const float4*)Vp)[(size_t)nb * 32 + lane];
        float p = q.x * k4.x + q.y * k4.y + q.z * k4.z + q.w * k4.w;
        p += __shfl_xor_sync(0xffffffffu, p, 1);
        p += __shfl_xor_sync(0xffffffffu, p, 2);
        d[j] = masked ? -1e30f : p * 0.25f;   // dh^-0.5 = 1/4
    }
    float m = d[0];
    #pragma unroll
    for (int j = 1; j < KNBR; j++) m = fmaxf(m, d[j]);
    float e[KNBR], s = 0.f;
    #pragma unroll
    for (int j = 0; j < KNBR; j++) { e[j] = __expf(d[j] - m); s += e[j]; }
    float inv = 1.f / s;
    float4 o = make_float4(0.f, 0.f, 0.f, 0.f);
    #pragma unroll
    for (int j = 0; j < KNBR; j++) {
        float a = e[j] * inv;
        o.x += a * v[j].x; o.y += a * v[j].y; o.z += a * v[j].z; o.w += a * v[j].w;
    }
    o.x = rnd_tf32(o.x); o.y = rnd_tf32(o.y);
    o.z = rnd_tf32(o.z); o.w = rnd_tf32(o.w);
    ((float4*)out)[(size_t)i * 32 + lane] = o;
}

// ---------------- host orchestration ----------------------------------------
extern "C" void kernel_launch(void* const* d_in, const int* in_sizes, int n_in,
                              void* d_out, int out_size) {
    const float* feat  = (const float*)d_in[0];
    const int*   nbr   = (const int*)d_in[1];
    const void*  valid = d_in[2];
    const float* wq1 = (const float*)d_in[3];
    const float* wk1 = (const float*)d_in[4];
    const float* wv1 = (const float*)d_in[5];
    const float* wo1 = (const float*)d_in[6];
    const float* bo1 = (const float*)d_in[7];
    const float* w1a = (const float*)d_in[8];
    const float* b1a = (const float*)d_in[9];
    const float* w1b = (const float*)d_in[10];
    const float* b1b = (const float*)d_in[11];
    const float* g1a = (const float*)d_in[12];
    const float* be1a= (const float*)d_in[13];
    const float* g1b = (const float*)d_in[14];
    const float* be1b= (const float*)d_in[15];
    const float* wq2 = (const float*)d_in[16];
    const float* wk2 = (const float*)d_in[17];
    const float* wv2 = (const float*)d_in[18];
    const float* wo2 = (const float*)d_in[19];
    const float* bo2 = (const float*)d_in[20];
    const float* w2a = (const float*)d_in[21];
    const float* b2a = (const float*)d_in[22];
    const float* w2b = (const float*)d_in[23];
    const float* b2b = (const float*)d_in[24];
    const float* g2a = (const float*)d_in[25];
    const float* be2a= (const float*)d_in[26];
    const float* g2b = (const float*)d_in[27];
    const float* be2b= (const float*)d_in[28];
    const float* w4  = (const float*)d_in[29];
    const float* b4  = (const float*)d_in[30];

    int N = in_sizes[0] / D;

    float *Q1, *K1, *V1, *K2, *V2, *Q2, *ATT, *XB, *RS, *WR;
    cudaGetSymbolAddress((void**)&Q1,  g_Q1);
    cudaGetSymbolAddress((void**)&K1,  g_K1);
    cudaGetSymbolAddress((void**)&V1,  g_V1);
    cudaGetSymbolAddress((void**)&K2,  g_K2);
    cudaGetSymbolAddress((void**)&V2,  g_V2);
    cudaGetSymbolAddress((void**)&Q2,  g_Q2);
    cudaGetSymbolAddress((void**)&ATT, g_ATT);
    cudaGetSymbolAddress((void**)&XB,  g_XB);
    cudaGetSymbolAddress((void**)&RS,  g_rs);
    cudaGetSymbolAddress((void**)&WR,  g_Wr);

    int MB64 = (N + 63) / 64;
    int WPB  = (N + 7) / 8;

    const int PROJ_SMEM  = (8 * 64 * 20 + 2 * 16 * 136) * 4;                   // 58368 B
    const int LAYER_SMEM = (2 * 8 * 64 * 20 + 2 * 16 * 136 + 64 * 4 * 2) * 4;  // 101376 B
    cudaFuncSetAttribute(proj5_kernel, cudaFuncAttributeMaxDynamicSharedMemorySize, PROJ_SMEM);
    cudaFuncSetAttribute(layer_kernel<128, 1, 0>, cudaFuncAttributeMaxDynamicSharedMemorySize, LAYER_SMEM);
    cudaFuncSetAttribute(layer_kernel<64, 0, 1>,  cudaFuncAttributeMaxDynamicSharedMemorySize, LAYER_SMEM);

    detect_valid_kernel<<<1, 1024>>>((const unsigned char*)valid, N * KNBR);

    // pre-round all mma weight operands to tf32
    PrepList pl;
    const float* srcs[13] = {wq1, wk1, wv1, wk2, wv2, wo1, w1a, w1b, wq2, wo2, w2a, w2b, w4};
    int lens[13] = {16384,16384,16384,16384,16384, 16384, 32768, 32768, 16384, 16384, 32768, 32768, 8192};
    int offs[13] = {OFF_WQ1,OFF_WK1,OFF_WV1,OFF_WK2,OFF_WV2, OFF_WO1, OFF_W1A, OFF_W1B,
                    OFF_WQ2, OFF_WO2, OFF_W2A, OFF_W2B, OFF_W4};
    for (int e = 0; e < 13; e++) { pl.src[e] = srcs[e]; pl.len[e] = lens[e]; pl.off[e] = offs[e]; }
    prep_weights<<<120, 256>>>(pl, WR);

    Proj5 p;
    p.W[0] = WR + OFF_WQ1; p.W[1] = WR + OFF_WK1; p.W[2] = WR + OFF_WV1;
    p.W[3] = WR + OFF_WK2; p.W[4] = WR + OFF_WV2;
    p.Y[0] = Q1;  p.Y[1] = K1;  p.Y[2] = V1;  p.Y[3] = K2;  p.Y[4] = V2;
    proj5_kernel<<<MB64, 256, PROJ_SMEM>>>(feat, p, RS, N);

    // ---- layer 1: writes XB (residual for layer 2) and Q2 = XB@wq2 ----
    attn_kernel<<<WPB, 256>>>(Q1, K1, V1, nbr, valid, RS, ATT, N);
    layer_kernel<128, 1, 0><<<MB64, 256, LAYER_SMEM>>>(
        ATT, WR + OFF_WO1, bo1, feat, g1a, be1a, WR + OFF_W1A, b1a, WR + OFF_W1B, b1b, g1b, be1b,
        WR + OFF_WQ2, nullptr, XB, Q2, N);

    // ---- layer 2: post = tanh(XB@w4 + b4) straight to d_out ----
    attn_kernel<<<WPB, 256>>>(Q2, K2, V2, nbr, valid, RS, ATT, N);
    layer_kernel<64, 0, 1><<<MB64, 256, LAYER_SMEM>>>(
        ATT, WR + OFF_WO2, bo2, XB, g2a, be2a, WR + OFF_W2A, b2a, WR + OFF_W2B, b2b, g2b, be2b,
        WR + OFF_W4, b4, nullptr, (float*)d_out, N);
}